// round 13
// baseline (speedup 1.0000x reference)
#include <cuda_runtime.h>
#include <cuda_fp16.h>
#include <cstdint>
#include <math.h>

// Problem constants (fixed shapes)
#define CN      100000
#define CE      1600000
#define CNFEAT  512
#define CNLABEL 64
#define CNHID   256
#define CHID2   512

// ---------------- scratch (device globals) ----------------------------------
__device__ float  g_tA  [(size_t)CN * CNHID];
__device__ float  g_tB  [(size_t)CN * CNHID];
__device__ __half g_h_hi[(size_t)CN * CNHID];
__device__ __half g_h_lo[(size_t)CN * CNHID];
__device__ __half g_m_hi[(size_t)CN * CHID2];
__device__ __half g_m_lo[(size_t)CN * CHID2];
__device__ __half g_x_hi[(size_t)CN * CNFEAT];
__device__ __half g_x_lo[(size_t)CN * CNFEAT];
__device__ __half g_w0t_hi[256 * 512], g_w0t_lo[256 * 512];
__device__ __half g_w1t_hi[256 * 256], g_w1t_lo[256 * 256];
__device__ __half g_w2t_hi[256 * 256], g_w2t_lo[256 * 256];
__device__ __half g_wm0t_hi[512 * 256], g_wm0t_lo[512 * 256];
__device__ __half g_wm1t_hi[64 * 512],  g_wm1t_lo[64 * 512];
__device__ float  g_dinv[CN];
__device__ int    g_cnt[CN];
__device__ int    g_rowptr[CN + 1];
__device__ int    g_cursor[CN];
__device__ int    g_src[CE];
__device__ float  g_w[CE];
__device__ int    g_lab[CN];

// ---------------- CSR build --------------------------------------------------
__global__ void k_zero_cnt(int n) {
    int i = blockIdx.x * blockDim.x + threadIdx.x;
    if (i < n) g_cnt[i] = 0;
}
__global__ void k_count(const int* __restrict__ adj, int E) {
    int e = blockIdx.x * blockDim.x + threadIdx.x;
    if (e >= E) return;
    atomicAdd(&g_cnt[adj[E + e]], 1);
}
__global__ void k_scan(int n, int E) {
    __shared__ int bs[1024];
    int tid = threadIdx.x;
    int chunk = (n + 1023) / 1024;
    int lo = tid * chunk;
    int hi = lo + chunk; if (hi > n) hi = n; if (lo > n) lo = n;
    int s = 0;
    for (int i = lo; i < hi; i++) s += g_cnt[i];
    int mysum = s;
    bs[tid] = s;
    __syncthreads();
    for (int d = 1; d < 1024; d <<= 1) {
        int v = (tid >= d) ? bs[tid - d] : 0;
        __syncthreads();
        bs[tid] += v;
        __syncthreads();
    }
    int off = bs[tid] - mysum;
    for (int i = lo; i < hi; i++) {
        g_rowptr[i] = off;
        g_cursor[i] = off;
        off += g_cnt[i];
    }
    if (tid == 1023) g_rowptr[n] = E;
}
__global__ void k_dinv(int n) {
    int i = blockIdx.x * blockDim.x + threadIdx.x;
    if (i < n) g_dinv[i] = rsqrtf((float)g_cnt[i] + 2.0f);
}
__global__ void k_fill(const int* __restrict__ adj, int E) {
    int e = blockIdx.x * blockDim.x + threadIdx.x;
    if (e >= E) return;
    int src = adj[e];
    int dst = adj[E + e];
    int pos = atomicAdd(&g_cursor[dst], 1);
    g_src[pos] = src;
    g_w[pos] = g_dinv[src] * g_dinv[dst];
}

// ---------------- labels ------------------------------------------------------
__global__ void k_lab_init(int n) {
    int i = blockIdx.x * blockDim.x + threadIdx.x;
    if (i < n) g_lab[i] = -1;
}
__global__ void k_lab_set(const int* __restrict__ idxl, const int* __restrict__ y, int L) {
    int t = blockIdx.x * blockDim.x + threadIdx.x;
    if (t >= L) return;
    int node = idxl[t];
    g_lab[node] = y[node];
}
__global__ void k_lab_add(const float* __restrict__ W0, float* __restrict__ t, int n) {
    int gt = blockIdx.x * blockDim.x + threadIdx.x;
    int warp = gt >> 5, lane = gt & 31;
    if (warp >= n) return;
    int lab = g_lab[warp];
    if (lab < 0) return;
    const float* wrow = W0 + (size_t)(CNFEAT + lab) * CNHID;
    float* trow = t + (size_t)warp * CNHID;
#pragma unroll
    for (int k = 0; k < CNHID / 32; k++)
        trow[k * 32 + lane] += wrow[k * 32 + lane];
}

// ---------------- split helpers ------------------------------------------------
__device__ __forceinline__ void split1(float v, __half& h, __half& l) {
    h = __float2half_rn(v);
    l = __float2half_rn(v - __half2float(h));
}

__global__ void k_split(const float* __restrict__ X, __half* __restrict__ H,
                        __half* __restrict__ L, long long nq) {
    long long i = (long long)blockIdx.x * blockDim.x + threadIdx.x;
    if (i >= nq) return;
    float4 v = ((const float4*)X)[i];
    __half2 h0 = __floats2half2_rn(v.x, v.y), h1 = __floats2half2_rn(v.z, v.w);
    float2 f0 = __half22float2(h0), f1 = __half22float2(h1);
    __half2 l0 = __floats2half2_rn(v.x - f0.x, v.y - f0.y);
    __half2 l1 = __floats2half2_rn(v.z - f1.x, v.w - f1.y);
    ((__half2*)H)[2 * i] = h0; ((__half2*)H)[2 * i + 1] = h1;
    ((__half2*)L)[2 * i] = l0; ((__half2*)L)[2 * i + 1] = l1;
}

__global__ void k_wt(const float* __restrict__ W, __half* __restrict__ TH,
                     __half* __restrict__ TL, int K, int N) {
    int idx = blockIdx.x * blockDim.x + threadIdx.x;
    if (idx >= N * K) return;
    int n = idx / K, k = idx % K;
    float v = W[(size_t)k * N + n];
    __half h, l;
    split1(v, h, l);
    TH[idx] = h;
    TL[idx] = l;
}

// ---------------- fused CSR aggregation (node range [n0, n1)) ------------------
__global__ void __launch_bounds__(256)
k_agg_csr(const float* __restrict__ t, __half* __restrict__ Oh, __half* __restrict__ Ol,
          const float* __restrict__ bias, int n0, int n1) {
    int warp = n0 + ((blockIdx.x * blockDim.x + threadIdx.x) >> 5);
    int lane = threadIdx.x & 31;
    if (warp >= n1) return;
    int beg = g_rowptr[warp];
    int end = g_rowptr[warp + 1];
    const float4* ti = (const float4*)(t + (size_t)warp * CNHID);
    const float4* bi = (const float4*)bias;
    float d = g_dinv[warp];
    float sw = 2.0f * d * d;

    float4 a0 = bi[lane], a1 = bi[32 + lane];
    float4 s0 = ti[lane], s1 = ti[32 + lane];
    a0.x += sw * s0.x; a0.y += sw * s0.y; a0.z += sw * s0.z; a0.w += sw * s0.w;
    a1.x += sw * s1.x; a1.y += sw * s1.y; a1.z += sw * s1.z; a1.w += sw * s1.w;

    int e = beg;
    for (; e + 1 < end; e += 2) {
        int sA = g_src[e], sB = g_src[e + 1];
        float wA = g_w[e], wB = g_w[e + 1];
        const float4* tA = (const float4*)(t + (size_t)sA * CNHID);
        const float4* tB = (const float4*)(t + (size_t)sB * CNHID);
        float4 vA0 = tA[lane], vA1 = tA[32 + lane];
        float4 vB0 = tB[lane], vB1 = tB[32 + lane];
        a0.x = fmaf(wA, vA0.x, a0.x); a0.y = fmaf(wA, vA0.y, a0.y);
        a0.z = fmaf(wA, vA0.z, a0.z); a0.w = fmaf(wA, vA0.w, a0.w);
        a1.x = fmaf(wA, vA1.x, a1.x); a1.y = fmaf(wA, vA1.y, a1.y);
        a1.z = fmaf(wA, vA1.z, a1.z); a1.w = fmaf(wA, vA1.w, a1.w);
        a0.x = fmaf(wB, vB0.x, a0.x); a0.y = fmaf(wB, vB0.y, a0.y);
        a0.z = fmaf(wB, vB0.z, a0.z); a0.w = fmaf(wB, vB0.w, a0.w);
        a1.x = fmaf(wB, vB1.x, a1.x); a1.y = fmaf(wB, vB1.y, a1.y);
        a1.z = fmaf(wB, vB1.z, a1.z); a1.w = fmaf(wB, vB1.w, a1.w);
    }
    if (e < end) {
        int sA = g_src[e];
        float wA = g_w[e];
        const float4* tA = (const float4*)(t + (size_t)sA * CNHID);
        float4 vA0 = tA[lane], vA1 = tA[32 + lane];
        a0.x = fmaf(wA, vA0.x, a0.x); a0.y = fmaf(wA, vA0.y, a0.y);
        a0.z = fmaf(wA, vA0.z, a0.z); a0.w = fmaf(wA, vA0.w, a0.w);
        a1.x = fmaf(wA, vA1.x, a1.x); a1.y = fmaf(wA, vA1.y, a1.y);
        a1.z = fmaf(wA, vA1.z, a1.z); a1.w = fmaf(wA, vA1.w, a1.w);
    }

    float v[8] = {fmaxf(a0.x, 0.f), fmaxf(a0.y, 0.f), fmaxf(a0.z, 0.f), fmaxf(a0.w, 0.f),
                  fmaxf(a1.x, 0.f), fmaxf(a1.y, 0.f), fmaxf(a1.z, 0.f), fmaxf(a1.w, 0.f)};
    __align__(8) __half hb[8], lb[8];
#pragma unroll
    for (int k = 0; k < 8; k++) split1(v[k], hb[k], lb[k]);
    size_t base = (size_t)warp * CNHID + 4 * lane;
    *(uint2*)&Oh[base]       = *(uint2*)&hb[0];
    *(uint2*)&Oh[base + 128] = *(uint2*)&hb[4];
    *(uint2*)&Ol[base]       = *(uint2*)&lb[0];
    *(uint2*)&Ol[base + 128] = *(uint2*)&lb[4];
}

// ---------------- log_softmax --------------------------------------------------
__global__ void k_logsoftmax64(float* __restrict__ out, int n) {
    int gt = blockIdx.x * blockDim.x + threadIdx.x;
    int warp = gt >> 5, lane = gt & 31;
    if (warp >= n) return;
    float* r = out + (size_t)warp * 64;
    float v0 = r[lane], v1 = r[lane + 32];
    float m = fmaxf(v0, v1);
#pragma unroll
    for (int o = 16; o; o >>= 1) m = fmaxf(m, __shfl_xor_sync(0xffffffffu, m, o));
    float s = expf(v0 - m) + expf(v1 - m);
#pragma unroll
    for (int o = 16; o; o >>= 1) s += __shfl_xor_sync(0xffffffffu, s, o);
    float l = m + logf(s);
    r[lane] = v0 - l;
    r[lane + 32] = v1 - l;
}

// ---------------- pre-split FP16 tensor-core GEMM (R7 config) ------------------
__device__ __forceinline__ void mma_f16(float* c, const uint32_t* a, const uint32_t* b) {
    asm volatile(
        "mma.sync.aligned.m16n8k16.row.col.f32.f16.f16.f32 "
        "{%0,%1,%2,%3}, {%4,%5,%6,%7}, {%8,%9}, {%0,%1,%2,%3};\n"
        : "+f"(c[0]), "+f"(c[1]), "+f"(c[2]), "+f"(c[3])
        : "r"(a[0]), "r"(a[1]), "r"(a[2]), "r"(a[3]), "r"(b[0]), "r"(b[1]));
}
__device__ __forceinline__ void ldsm4(uint32_t& r0, uint32_t& r1, uint32_t& r2,
                                      uint32_t& r3, uint32_t addr) {
    asm volatile("ldmatrix.sync.aligned.m8n8.x4.shared.b16 {%0,%1,%2,%3}, [%4];"
                 : "=r"(r0), "=r"(r1), "=r"(r2), "=r"(r3) : "r"(addr));
}
__device__ __forceinline__ uint32_t s2u(const void* p) {
    uint32_t a;
    asm("{ .reg .u64 t; cvta.to.shared.u64 t, %1; cvt.u32.u64 %0, t; }" : "=r"(a) : "l"(p));
    return a;
}
__device__ __forceinline__ void cpa16(uint32_t dst, const void* src, bool pred) {
    asm volatile("cp.async.cg.shared.global [%0], [%1], 16, %2;"
                 :: "r"(dst), "l"(src), "r"(pred ? 16 : 0) : "memory");
}
__device__ __forceinline__ void cpa_commit() {
    asm volatile("cp.async.commit_group;" ::: "memory");
}
__device__ __forceinline__ void cpa_wait0() {
    asm volatile("cp.async.wait_group 0;" ::: "memory");
}

// C[M,N] = A @ B; A (hi,lo) f16 [M][K]; B transposed (hi,lo) f16 [N][K].
// BM=128, BK=32. EPI: 0 plain fp32 | 1 bias+ELU -> split (Oh,Ol) | 2 bias fp32
template <int BN, int EPI>
__global__ void __launch_bounds__(256)
k_hgemm(const __half* __restrict__ Ah, const __half* __restrict__ Al,
        const __half* __restrict__ Bh, const __half* __restrict__ Bl,
        float* __restrict__ C, const float* __restrict__ bias,
        __half* __restrict__ Oh, __half* __restrict__ Ol,
        int M, int N, int K) {
    constexpr int RSTR  = 80;                 // 64B data + 16B pad
    constexpr int ATILE = 128 * RSTR;
    constexpr int ABUF  = 2 * ATILE;
    constexpr int BTILE = BN * RSTR;
    constexpr int BBUF  = 2 * BTILE;
    constexpr int OFFB  = 2 * ABUF;
    constexpr int NWN   = BN / 32;
    constexpr int MT    = (128 / (8 / NWN)) / 16;

    extern __shared__ char smem[];
    const uint32_t sb = s2u(smem);
    const int tid = threadIdx.x;
    const int wid = tid >> 5, lane = tid & 31;
    const int grp = lane >> 2, qid = lane & 3;
    const int warp_m = wid / NWN, warp_n = wid % NWN;
    const int row0 = blockIdx.y * 128;
    const int col0 = blockIdx.x * BN;

    const int lrow = lane & 15;
    const int lcol = (lane >> 4) * 16;

    float acc[MT][4][4];
#pragma unroll
    for (int i = 0; i < MT; i++)
#pragma unroll
        for (int j = 0; j < 4; j++)
#pragma unroll
            for (int c = 0; c < 4; c++) acc[i][j][c] = 0.0f;

    auto loadSlab = [&](int s, int b) {
        int k0 = s * 32;
#pragma unroll
        for (int i = 0; i < 2; i++) {
            int c = tid + i * 256;
            int r = c >> 2, p = c & 3;
            bool ok = (row0 + r) < M;
            int rr = ok ? (row0 + r) : (M - 1);
            size_t g = (size_t)rr * K + k0 + p * 8;
            uint32_t dst = sb + b * ABUF + r * RSTR + p * 16;
            cpa16(dst,         Ah + g, ok);
            cpa16(dst + ATILE, Al + g, ok);
        }
#pragma unroll
        for (int i = 0; i < BN / 64; i++) {
            int c = tid + i * 256;
            int r = c >> 2, p = c & 3;
            size_t g = (size_t)(col0 + r) * K + k0 + p * 8;
            uint32_t dst = sb + OFFB + b * BBUF + r * RSTR + p * 16;
            cpa16(dst,         Bh + g, true);
            cpa16(dst + BTILE, Bl + g, true);
        }
        cpa_commit();
    };

    auto computeSlab = [&](int b) {
        const uint32_t aB = sb + b * ABUF;
        const uint32_t bB = sb + OFFB + b * BBUF;
#pragma unroll
        for (int ks = 0; ks < 2; ks++) {
            const int kb = ks * 32 + lcol;
            uint32_t bh[4][2], bl[4][2];
#pragma unroll
            for (int p = 0; p < 2; p++) {
                uint32_t addr = bB + (warp_n * 32 + p * 16 + lrow) * RSTR + kb;
                ldsm4(bh[2 * p][0], bh[2 * p + 1][0], bh[2 * p][1], bh[2 * p + 1][1], addr);
                ldsm4(bl[2 * p][0], bl[2 * p + 1][0], bl[2 * p][1], bl[2 * p + 1][1],
                      addr + BTILE);
            }
#pragma unroll
            for (int mt = 0; mt < MT; mt++) {
                uint32_t addr = aB + (warp_m * (MT * 16) + mt * 16 + lrow) * RSTR + kb;
                uint32_t ah[4], al[4];
                ldsm4(ah[0], ah[1], ah[2], ah[3], addr);
                ldsm4(al[0], al[1], al[2], al[3], addr + ATILE);
#pragma unroll
                for (int nt = 0; nt < 4; nt++) {
                    mma_f16(acc[mt][nt], ah, bh[nt]);   // hi*hi
                    mma_f16(acc[mt][nt], ah, bl[nt]);   // hi*lo
                    mma_f16(acc[mt][nt], al, bh[nt]);   // lo*hi
                }
            }
        }
    };

    const int ns = K / 32;
    loadSlab(0, 0);
    cpa_wait0();
    __syncthreads();
    for (int s = 0; s < ns; s++) {
        int b = s & 1;
        if (s + 1 < ns) loadSlab(s + 1, b ^ 1);
        computeSlab(b);
        if (s + 1 < ns) {
            cpa_wait0();
            __syncthreads();
        }
    }

    // ---- epilogue ----
#pragma unroll
    for (int mt = 0; mt < MT; mt++) {
        int rbase = row0 + warp_m * (MT * 16) + mt * 16 + grp;
#pragma unroll
        for (int nt = 0; nt < 4; nt++) {
            int cb = col0 + warp_n * 32 + nt * 8 + 2 * qid;
#pragma unroll
            for (int half = 0; half < 2; half++) {
                int r = rbase + half * 8;
                if (r >= M) continue;
                float v0 = acc[mt][nt][half * 2 + 0];
                float v1 = acc[mt][nt][half * 2 + 1];
                if (EPI >= 1) { v0 += bias[cb]; v1 += bias[cb + 1]; }
                if (EPI == 1) {
                    v0 = v0 > 0.0f ? v0 : expm1f(v0);
                    v1 = v1 > 0.0f ? v1 : expm1f(v1);
                    __half h0, l0, h1, l1;
                    split1(v0, h0, l0);
                    split1(v1, h1, l1);
                    size_t base = (size_t)r * N + cb;
                    *(__half2*)&Oh[base] = __halves2half2(h0, h1);
                    *(__half2*)&Ol[base] = __halves2half2(l0, l1);
                } else {
                    *(float2*)&C[(size_t)r * N + cb] = make_float2(v0, v1);
                }
            }
        }
    }
}

// ---------------- host orchestration ---------------------------------------
static inline int cdiv(long long a, long long b) { return (int)((a + b - 1) / b); }

extern "C" void kernel_launch(void* const* d_in, const int* in_sizes, int n_in,
                              void* d_out, int out_size) {
    const float* x    = (const float*)d_in[0];
    const int*   y    = (const int*)  d_in[1];
    const int*   adj  = (const int*)  d_in[3];
    const int*   idxl = (const int*)  d_in[4];
    const float* W0  = (const float*)d_in[6];
    const float* b0  = (const float*)d_in[7];
    const float* W1  = (const float*)d_in[8];
    const float* b1  = (const float*)d_in[9];
    const float* W2  = (const float*)d_in[10];
    const float* b2  = (const float*)d_in[11];
    const float* Wm0 = (const float*)d_in[12];
    const float* bm0 = (const float*)d_in[13];
    const float* Wm1 = (const float*)d_in[14];
    const float* bm1 = (const float*)d_in[15];

    int N = in_sizes[1];
    int E = in_sizes[3] / 2;
    int L = in_sizes[4];
    float* out = (float*)d_out;

    float *p_tA, *p_tB;
    __half *p_hh, *p_hl, *p_mh, *p_ml, *p_xh, *p_xl;
    __half *w0h, *w0l, *w1h, *w1l, *w2h, *w2l, *wm0h, *wm0l, *wm1h, *wm1l;
    cudaGetSymbolAddress((void**)&p_tA, g_tA);
    cudaGetSymbolAddress((void**)&p_tB, g_tB);
    cudaGetSymbolAddress((void**)&p_hh, g_h_hi);
    cudaGetSymbolAddress((void**)&p_hl, g_h_lo);
    cudaGetSymbolAddress((void**)&p_mh, g_m_hi);
    cudaGetSymbolAddress((void**)&p_ml, g_m_lo);
    cudaGetSymbolAddress((void**)&p_xh, g_x_hi);
    cudaGetSymbolAddress((void**)&p_xl, g_x_lo);
    cudaGetSymbolAddress((void**)&w0h,  g_w0t_hi);  cudaGetSymbolAddress((void**)&w0l,  g_w0t_lo);
    cudaGetSymbolAddress((void**)&w1h,  g_w1t_hi);  cudaGetSymbolAddress((void**)&w1l,  g_w1t_lo);
    cudaGetSymbolAddress((void**)&w2h,  g_w2t_hi);  cudaGetSymbolAddress((void**)&w2l,  g_w2t_lo);
    cudaGetSymbolAddress((void**)&wm0h, g_wm0t_hi); cudaGetSymbolAddress((void**)&wm0l, g_wm0t_lo);
    cudaGetSymbolAddress((void**)&wm1h, g_wm1t_hi); cudaGetSymbolAddress((void**)&wm1l, g_wm1t_lo);

    // lazy one-time stream/event creation (outside capture on the correctness call)
    static cudaStream_t s1 = nullptr;
    static cudaEvent_t ev[12];
    if (s1 == nullptr) {
        cudaStreamCreateWithFlags(&s1, cudaStreamNonBlocking);
        for (int i = 0; i < 12; i++) cudaEventCreateWithFlags(&ev[i], cudaEventDisableTiming);
    }

    const int TB = 256;
    const int SMEM128 = 2 * 2 * 128 * 80 + 2 * 2 * 128 * 80;   // 81920
    const int SMEM64  = 2 * 2 * 128 * 80 + 2 * 2 * 64 * 80;    // 61440
    cudaFuncSetAttribute(k_hgemm<128, 0>, cudaFuncAttributeMaxDynamicSharedMemorySize, SMEM128);
    cudaFuncSetAttribute(k_hgemm<128, 1>, cudaFuncAttributeMaxDynamicSharedMemorySize, SMEM128);
    cudaFuncSetAttribute(k_hgemm<64, 2>,  cudaFuncAttributeMaxDynamicSharedMemorySize, SMEM64);

    long long xq = (long long)N * CNFEAT / 4;
    long long nwcell = (long long)N * 32;
    int gy = cdiv(N, 128);

    // node chunks (half the 128-row blocks each)
    const int gy0 = gy / 2;                 // blocks in chunk0
    const int C0  = gy0 * 128;              // rows in chunk0
    const int gy1 = gy - gy0;               // blocks in chunk1
    const int C1r = N - C0;                 // rows in chunk1
    long long c0cell = (long long)C0 * 32;
    long long c1cell = (long long)C1r * 32;

    // ---- fork: prep branch on s1 runs concurrently with split/wt0/GEMM1 ----
    cudaEventRecord(ev[0], 0);
    cudaStreamWaitEvent(s1, ev[0], 0);

    // stream 0: GEMM1 dependency chain
    k_split<<<cdiv(xq, TB), TB>>>(x, p_xh, p_xl, xq);
    k_wt<<<cdiv(256 * 512, TB), TB>>>(W0, w0h, w0l, 512, 256);
    k_hgemm<128, 0><<<dim3(2, gy), 256, SMEM128>>>(p_xh, p_xl, w0h, w0l,
                                                   p_tA, nullptr, nullptr, nullptr,
                                                   N, 256, 512);

    // stream s1: everything independent of GEMM1
    k_wt<<<cdiv(256 * 256, TB), TB, 0, s1>>>(W1, w1h, w1l, 256, 256);
    k_wt<<<cdiv(256 * 256, TB), TB, 0, s1>>>(W2, w2h, w2l, 256, 256);
    k_wt<<<cdiv(512 * 256, TB), TB, 0, s1>>>(Wm0, wm0h, wm0l, 256, 512);
    k_wt<<<cdiv(64 * 512, TB), TB, 0, s1>>>(Wm1, wm1h, wm1l, 512, 64);
    k_lab_init<<<cdiv(N, TB), TB, 0, s1>>>(N);
    k_lab_set<<<cdiv(L, TB), TB, 0, s1>>>(idxl, y, L);
    k_zero_cnt<<<cdiv(N, TB), TB, 0, s1>>>(N);
    k_count<<<cdiv(E, TB), TB, 0, s1>>>(adj, E);
    k_scan<<<1, 1024, 0, s1>>>(N, E);
    k_dinv<<<cdiv(N, TB), TB, 0, s1>>>(N);
    k_fill<<<cdiv(E, TB), TB, 0, s1>>>(adj, E);

    cudaEventRecord(ev[1], s1);
    cudaStreamWaitEvent(0, ev[1], 0);

    // layer 1 finish: labels into tA
    k_lab_add<<<cdiv(nwcell, TB), TB>>>(W0, p_tA, N);

    // ---- boundary 1: agg1(tA) chunks pipelined with GEMM2 chunks (-> tB) ----
    k_agg_csr<<<cdiv(c0cell, TB), TB>>>(p_tA, p_hh, p_hl, b0, 0, C0);
    cudaEventRecord(ev[2], 0);
    cudaStreamWaitEvent(s1, ev[2], 0);
    k_hgemm<128, 0><<<dim3(2, gy0), 256, SMEM128, s1>>>(p_hh, p_hl, w1h, w1l,
                                                        p_tB, nullptr, nullptr, nullptr,
                                                        C0, 256, 256);
    k_agg_csr<<<cdiv(c1cell, TB), TB>>>(p_tA, p_hh, p_hl, b0, C0, N);
    cudaEventRecord(ev[3], 0);
    cudaStreamWaitEvent(s1, ev[3], 0);
    k_hgemm<128, 0><<<dim3(2, gy1), 256, SMEM128, s1>>>(p_hh + (size_t)C0 * CNHID,
                                                        p_hl + (size_t)C0 * CNHID,
                                                        w1h, w1l,
                                                        p_tB + (size_t)C0 * CNHID,
                                                        nullptr, nullptr, nullptr,
                                                        C1r, 256, 256);
    cudaEventRecord(ev[4], s1);
    cudaStreamWaitEvent(0, ev[4], 0);

    // ---- boundary 2: agg2(tB) pipelined with GEMM3 chunks (-> tA) ----
    k_agg_csr<<<cdiv(c0cell, TB), TB>>>(p_tB, p_hh, p_hl, b1, 0, C0);
    cudaEventRecord(ev[5], 0);
    cudaStreamWaitEvent(s1, ev[5], 0);
    k_hgemm<128, 0><<<dim3(2, gy0), 256, SMEM128, s1>>>(p_hh, p_hl, w2h, w2l,
                                                        p_tA, nullptr, nullptr, nullptr,
                                                        C0, 256, 256);
    k_agg_csr<<<cdiv(c1cell, TB), TB>>>(p_tB, p_hh, p_hl, b1, C0, N);
    cudaEventRecord(ev[6], 0);
    cudaStreamWaitEvent(s1, ev[6], 0);
    k_hgemm<128, 0><<<dim3(2, gy1), 256, SMEM128, s1>>>(p_hh + (size_t)C0 * CNHID,
                                                        p_hl + (size_t)C0 * CNHID,
                                                        w2h, w2l,
                                                        p_tA + (size_t)C0 * CNHID,
                                                        nullptr, nullptr, nullptr,
                                                        C1r, 256, 256);
    cudaEventRecord(ev[7], s1);
    cudaStreamWaitEvent(0, ev[7], 0);

    // ---- boundary 3: agg3(tA) pipelined with MLP1 chunks (-> m hi/lo) ----
    k_agg_csr<<<cdiv(c0cell, TB), TB>>>(p_tA, p_hh, p_hl, b2, 0, C0);
    cudaEventRecord(ev[8], 0);
    cudaStreamWaitEvent(s1, ev[8], 0);
    k_hgemm<128, 1><<<dim3(4, gy0), 256, SMEM128, s1>>>(p_hh, p_hl, wm0h, wm0l,
                                                        nullptr, bm0, p_mh, p_ml,
                                                        C0, 512, 256);
    k_agg_csr<<<cdiv(c1cell, TB), TB>>>(p_tA, p_hh, p_hl, b2, C0, N);
    cudaEventRecord(ev[9], 0);
    cudaStreamWaitEvent(s1, ev[9], 0);
    k_hgemm<128, 1><<<dim3(4, gy1), 256, SMEM128, s1>>>(p_hh + (size_t)C0 * CNHID,
                                                        p_hl + (size_t)C0 * CNHID,
                                                        wm0h, wm0l,
                                                        nullptr, bm0,
                                                        p_mh + (size_t)C0 * CHID2,
                                                        p_ml + (size_t)C0 * CHID2,
                                                        C1r, 512, 256);
    cudaEventRecord(ev[10], s1);
    cudaStreamWaitEvent(0, ev[10], 0);

    // ---- MLP2 + log_softmax (serial) ----
    k_hgemm<64, 2><<<dim3(1, gy), 256, SMEM64>>>(p_mh, p_ml, wm1h, wm1l,
                                                 out, bm1, nullptr, nullptr,
                                                 N, 64, 512);
    k_logsoftmax64<<<cdiv(nwcell, TB), TB>>>(out, N);
}

// round 14
// speedup vs baseline: 1.2444x; 1.2444x over previous
#include <cuda_runtime.h>
#include <cuda_fp16.h>
#include <cstdint>
#include <math.h>

// Problem constants (fixed shapes)
#define CN      100000
#define CE      1600000
#define CNFEAT  512
#define CNLABEL 64
#define CNHID   256
#define CHID2   512

// ---------------- scratch (device globals) ----------------------------------
__device__ float  g_t   [(size_t)CN * CNHID];
__device__ __half g_h_hi[(size_t)CN * CNHID];
__device__ __half g_m_hi[(size_t)CN * CHID2];
__device__ __half g_x_hi[(size_t)CN * CNFEAT];
__device__ __half g_w0t_hi[256 * 512], g_w0t_lo[256 * 512];
__device__ __half g_w1t_hi[256 * 256], g_w1t_lo[256 * 256];
__device__ __half g_w2t_hi[256 * 256], g_w2t_lo[256 * 256];
__device__ __half g_wm0t_hi[512 * 256], g_wm0t_lo[512 * 256];
__device__ __half g_wm1t_hi[64 * 512],  g_wm1t_lo[64 * 512];
__device__ float  g_dinv[CN];
__device__ int    g_cnt[CN];
__device__ int    g_rowptr[CN + 1];
__device__ int    g_cursor[CN];
__device__ int    g_src[CE];
__device__ float  g_w[CE];
__device__ int    g_lab[CN];

// ---------------- CSR build --------------------------------------------------
__global__ void k_zero_cnt(int n) {
    int i = blockIdx.x * blockDim.x + threadIdx.x;
    if (i < n) g_cnt[i] = 0;
}
__global__ void k_count(const int* __restrict__ adj, int E) {
    int e = blockIdx.x * blockDim.x + threadIdx.x;
    if (e >= E) return;
    atomicAdd(&g_cnt[adj[E + e]], 1);
}
__global__ void k_scan(int n, int E) {
    __shared__ int bs[1024];
    int tid = threadIdx.x;
    int chunk = (n + 1023) / 1024;
    int lo = tid * chunk;
    int hi = lo + chunk; if (hi > n) hi = n; if (lo > n) lo = n;
    int s = 0;
    for (int i = lo; i < hi; i++) s += g_cnt[i];
    int mysum = s;
    bs[tid] = s;
    __syncthreads();
    for (int d = 1; d < 1024; d <<= 1) {
        int v = (tid >= d) ? bs[tid - d] : 0;
        __syncthreads();
        bs[tid] += v;
        __syncthreads();
    }
    int off = bs[tid] - mysum;
    for (int i = lo; i < hi; i++) {
        g_rowptr[i] = off;
        g_cursor[i] = off;
        off += g_cnt[i];
    }
    if (tid == 1023) g_rowptr[n] = E;
}
__global__ void k_dinv(int n) {
    int i = blockIdx.x * blockDim.x + threadIdx.x;
    if (i < n) g_dinv[i] = rsqrtf((float)g_cnt[i] + 2.0f);
}
__global__ void k_fill(const int* __restrict__ adj, int E) {
    int e = blockIdx.x * blockDim.x + threadIdx.x;
    if (e >= E) return;
    int src = adj[e];
    int dst = adj[E + e];
    int pos = atomicAdd(&g_cursor[dst], 1);
    g_src[pos] = src;
    g_w[pos] = g_dinv[src] * g_dinv[dst];
}

// ---------------- labels ------------------------------------------------------
__global__ void k_lab_init(int n) {
    int i = blockIdx.x * blockDim.x + threadIdx.x;
    if (i < n) g_lab[i] = -1;
}
__global__ void k_lab_set(const int* __restrict__ idxl, const int* __restrict__ y, int L) {
    int t = blockIdx.x * blockDim.x + threadIdx.x;
    if (t >= L) return;
    int node = idxl[t];
    g_lab[node] = y[node];
}
__global__ void k_lab_add(const float* __restrict__ W0, float* __restrict__ t, int n) {
    int gt = blockIdx.x * blockDim.x + threadIdx.x;
    int warp = gt >> 5, lane = gt & 31;
    if (warp >= n) return;
    int lab = g_lab[warp];
    if (lab < 0) return;
    const float* wrow = W0 + (size_t)(CNFEAT + lab) * CNHID;
    float* trow = t + (size_t)warp * CNHID;
#pragma unroll
    for (int k = 0; k < CNHID / 32; k++)
        trow[k * 32 + lane] += wrow[k * 32 + lane];
}

// ---------------- split helpers ------------------------------------------------
__device__ __forceinline__ void split1(float v, __half& h, __half& l) {
    h = __float2half_rn(v);
    l = __float2half_rn(v - __half2float(h));
}

// activations: plain fp16 cast (hi only — residual term dropped in GEMM)
__global__ void k_cast16(const float* __restrict__ X, __half* __restrict__ H, long long nq) {
    long long i = (long long)blockIdx.x * blockDim.x + threadIdx.x;
    if (i >= nq) return;
    float4 v = ((const float4*)X)[i];
    ((__half2*)H)[2 * i]     = __floats2half2_rn(v.x, v.y);
    ((__half2*)H)[2 * i + 1] = __floats2half2_rn(v.z, v.w);
}

// weights: transpose + exact hi/lo split (kept 2-term accurate)
__global__ void k_wt(const float* __restrict__ W, __half* __restrict__ TH,
                     __half* __restrict__ TL, int K, int N) {
    int idx = blockIdx.x * blockDim.x + threadIdx.x;
    if (idx >= N * K) return;
    int n = idx / K, k = idx % K;
    float v = W[(size_t)k * N + n];
    __half h, l;
    split1(v, h, l);
    TH[idx] = h;
    TL[idx] = l;
}

// ---------------- fused CSR aggregation --------------------------------------
__global__ void __launch_bounds__(256)
k_agg_csr(const float* __restrict__ t, __half* __restrict__ Oh,
          const float* __restrict__ bias, int n) {
    int warp = (blockIdx.x * blockDim.x + threadIdx.x) >> 5;
    int lane = threadIdx.x & 31;
    if (warp >= n) return;
    int beg = g_rowptr[warp];
    int end = g_rowptr[warp + 1];
    const float4* ti = (const float4*)(t + (size_t)warp * CNHID);
    const float4* bi = (const float4*)bias;
    float d = g_dinv[warp];
    float sw = 2.0f * d * d;

    float4 a0 = bi[lane], a1 = bi[32 + lane];
    float4 s0 = ti[lane], s1 = ti[32 + lane];
    a0.x += sw * s0.x; a0.y += sw * s0.y; a0.z += sw * s0.z; a0.w += sw * s0.w;
    a1.x += sw * s1.x; a1.y += sw * s1.y; a1.z += sw * s1.z; a1.w += sw * s1.w;

    int e = beg;
    for (; e + 1 < end; e += 2) {
        int sA = g_src[e], sB = g_src[e + 1];
        float wA = g_w[e], wB = g_w[e + 1];
        const float4* tA = (const float4*)(t + (size_t)sA * CNHID);
        const float4* tB = (const float4*)(t + (size_t)sB * CNHID);
        float4 vA0 = tA[lane], vA1 = tA[32 + lane];
        float4 vB0 = tB[lane], vB1 = tB[32 + lane];
        a0.x = fmaf(wA, vA0.x, a0.x); a0.y = fmaf(wA, vA0.y, a0.y);
        a0.z = fmaf(wA, vA0.z, a0.z); a0.w = fmaf(wA, vA0.w, a0.w);
        a1.x = fmaf(wA, vA1.x, a1.x); a1.y = fmaf(wA, vA1.y, a1.y);
        a1.z = fmaf(wA, vA1.z, a1.z); a1.w = fmaf(wA, vA1.w, a1.w);
        a0.x = fmaf(wB, vB0.x, a0.x); a0.y = fmaf(wB, vB0.y, a0.y);
        a0.z = fmaf(wB, vB0.z, a0.z); a0.w = fmaf(wB, vB0.w, a0.w);
        a1.x = fmaf(wB, vB1.x, a1.x); a1.y = fmaf(wB, vB1.y, a1.y);
        a1.z = fmaf(wB, vB1.z, a1.z); a1.w = fmaf(wB, vB1.w, a1.w);
    }
    if (e < end) {
        int sA = g_src[e];
        float wA = g_w[e];
        const float4* tA = (const float4*)(t + (size_t)sA * CNHID);
        float4 vA0 = tA[lane], vA1 = tA[32 + lane];
        a0.x = fmaf(wA, vA0.x, a0.x); a0.y = fmaf(wA, vA0.y, a0.y);
        a0.z = fmaf(wA, vA0.z, a0.z); a0.w = fmaf(wA, vA0.w, a0.w);
        a1.x = fmaf(wA, vA1.x, a1.x); a1.y = fmaf(wA, vA1.y, a1.y);
        a1.z = fmaf(wA, vA1.z, a1.z); a1.w = fmaf(wA, vA1.w, a1.w);
    }

    // relu + fp16 cast (hi only)
    __half2 o0 = __floats2half2_rn(fmaxf(a0.x, 0.f), fmaxf(a0.y, 0.f));
    __half2 o1 = __floats2half2_rn(fmaxf(a0.z, 0.f), fmaxf(a0.w, 0.f));
    __half2 o2 = __floats2half2_rn(fmaxf(a1.x, 0.f), fmaxf(a1.y, 0.f));
    __half2 o3 = __floats2half2_rn(fmaxf(a1.z, 0.f), fmaxf(a1.w, 0.f));
    size_t base = (size_t)warp * CNHID + 4 * lane;
    __half2* hp = (__half2*)&Oh[base];
    hp[0] = o0; hp[1] = o1;
    __half2* hp2 = (__half2*)&Oh[base + 128];
    hp2[0] = o2; hp2[1] = o3;
}

// ---------------- log_softmax --------------------------------------------------
__global__ void k_logsoftmax64(float* __restrict__ out, int n) {
    int gt = blockIdx.x * blockDim.x + threadIdx.x;
    int warp = gt >> 5, lane = gt & 31;
    if (warp >= n) return;
    float* r = out + (size_t)warp * 64;
    float v0 = r[lane], v1 = r[lane + 32];
    float m = fmaxf(v0, v1);
#pragma unroll
    for (int o = 16; o; o >>= 1) m = fmaxf(m, __shfl_xor_sync(0xffffffffu, m, o));
    float s = expf(v0 - m) + expf(v1 - m);
#pragma unroll
    for (int o = 16; o; o >>= 1) s += __shfl_xor_sync(0xffffffffu, s, o);
    float l = m + logf(s);
    r[lane] = v0 - l;
    r[lane + 32] = v1 - l;
}

// ---------------- 2-term FP16 tensor-core GEMM ---------------------------------
// C[M,N] ≈ A_hi @ (B_hi + B_lo): weights exactly split, activation residual dropped.
__device__ __forceinline__ void mma_f16(float* c, const uint32_t* a, const uint32_t* b) {
    asm volatile(
        "mma.sync.aligned.m16n8k16.row.col.f32.f16.f16.f32 "
        "{%0,%1,%2,%3}, {%4,%5,%6,%7}, {%8,%9}, {%0,%1,%2,%3};\n"
        : "+f"(c[0]), "+f"(c[1]), "+f"(c[2]), "+f"(c[3])
        : "r"(a[0]), "r"(a[1]), "r"(a[2]), "r"(a[3]), "r"(b[0]), "r"(b[1]));
}
__device__ __forceinline__ void ldsm4(uint32_t& r0, uint32_t& r1, uint32_t& r2,
                                      uint32_t& r3, uint32_t addr) {
    asm volatile("ldmatrix.sync.aligned.m8n8.x4.shared.b16 {%0,%1,%2,%3}, [%4];"
                 : "=r"(r0), "=r"(r1), "=r"(r2), "=r"(r3) : "r"(addr));
}
__device__ __forceinline__ uint32_t s2u(const void* p) {
    uint32_t a;
    asm("{ .reg .u64 t; cvta.to.shared.u64 t, %1; cvt.u32.u64 %0, t; }" : "=r"(a) : "l"(p));
    return a;
}
__device__ __forceinline__ void cpa16(uint32_t dst, const void* src, bool pred) {
    asm volatile("cp.async.cg.shared.global [%0], [%1], 16, %2;"
                 :: "r"(dst), "l"(src), "r"(pred ? 16 : 0) : "memory");
}
__device__ __forceinline__ void cpa_commit() {
    asm volatile("cp.async.commit_group;" ::: "memory");
}
__device__ __forceinline__ void cpa_wait0() {
    asm volatile("cp.async.wait_group 0;" ::: "memory");
}

// A_hi f16 [M][K]; B transposed (hi,lo) f16 [N][K]. BM=128, BK=32, 256 threads.
// EPI: 0 plain fp32 | 1 bias+ELU -> fp16 Oh | 2 bias fp32
template <int BN, int EPI>
__global__ void __launch_bounds__(256)
k_hgemm(const __half* __restrict__ Ah,
        const __half* __restrict__ Bh, const __half* __restrict__ Bl,
        float* __restrict__ C, const float* __restrict__ bias,
        __half* __restrict__ Oh,
        int M, int N, int K) {
    constexpr int RSTR  = 80;                 // 64B data + 16B pad
    constexpr int ATILE = 128 * RSTR;         // 10240 (hi only)
    constexpr int BTILE = BN * RSTR;
    constexpr int BBUF  = 2 * BTILE;          // hi + lo
    constexpr int OFFB  = 2 * ATILE;          // after 2 A buffers
    constexpr int NWN   = BN / 32;
    constexpr int MT    = (128 / (8 / NWN)) / 16;

    extern __shared__ char smem[];
    const uint32_t sb = s2u(smem);
    const int tid = threadIdx.x;
    const int wid = tid >> 5, lane = tid & 31;
    const int grp = lane >> 2, qid = lane & 3;
    const int warp_m = wid / NWN, warp_n = wid % NWN;
    const int row0 = blockIdx.y * 128;
    const int col0 = blockIdx.x * BN;

    const int lrow = lane & 15;
    const int lcol = (lane >> 4) * 16;

    float acc[MT][4][4];
#pragma unroll
    for (int i = 0; i < MT; i++)
#pragma unroll
        for (int j = 0; j < 4; j++)
#pragma unroll
            for (int c = 0; c < 4; c++) acc[i][j][c] = 0.0f;

    auto loadSlab = [&](int s, int b) {
        int k0 = s * 32;
#pragma unroll
        for (int i = 0; i < 2; i++) {
            int c = tid + i * 256;
            int r = c >> 2, p = c & 3;
            bool ok = (row0 + r) < M;
            int rr = ok ? (row0 + r) : (M - 1);
            size_t g = (size_t)rr * K + k0 + p * 8;
            uint32_t dst = sb + b * ATILE + r * RSTR + p * 16;
            cpa16(dst, Ah + g, ok);
        }
#pragma unroll
        for (int i = 0; i < BN / 64; i++) {
            int c = tid + i * 256;
            int r = c >> 2, p = c & 3;
            size_t g = (size_t)(col0 + r) * K + k0 + p * 8;
            uint32_t dst = sb + OFFB + b * BBUF + r * RSTR + p * 16;
            cpa16(dst,         Bh + g, true);
            cpa16(dst + BTILE, Bl + g, true);
        }
        cpa_commit();
    };

    auto computeSlab = [&](int b) {
        const uint32_t aB = sb + b * ATILE;
        const uint32_t bB = sb + OFFB + b * BBUF;
#pragma unroll
        for (int ks = 0; ks < 2; ks++) {
            const int kb = ks * 32 + lcol;
            uint32_t bh[4][2], bl[4][2];
#pragma unroll
            for (int p = 0; p < 2; p++) {
                uint32_t addr = bB + (warp_n * 32 + p * 16 + lrow) * RSTR + kb;
                ldsm4(bh[2 * p][0], bh[2 * p + 1][0], bh[2 * p][1], bh[2 * p + 1][1], addr);
                ldsm4(bl[2 * p][0], bl[2 * p + 1][0], bl[2 * p][1], bl[2 * p + 1][1],
                      addr + BTILE);
            }
#pragma unroll
            for (int mt = 0; mt < MT; mt++) {
                uint32_t addr = aB + (warp_m * (MT * 16) + mt * 16 + lrow) * RSTR + kb;
                uint32_t ah[4];
                ldsm4(ah[0], ah[1], ah[2], ah[3], addr);
#pragma unroll
                for (int nt = 0; nt < 4; nt++) {
                    mma_f16(acc[mt][nt], ah, bh[nt]);   // hi*hi
                    mma_f16(acc[mt][nt], ah, bl[nt]);   // hi*lo (weight residual)
                }
            }
        }
    };

    const int ns = K / 32;
    loadSlab(0, 0);
    cpa_wait0();
    __syncthreads();
    for (int s = 0; s < ns; s++) {
        int b = s & 1;
        if (s + 1 < ns) loadSlab(s + 1, b ^ 1);
        computeSlab(b);
        if (s + 1 < ns) {
            cpa_wait0();
            __syncthreads();
        }
    }

    // ---- epilogue ----
#pragma unroll
    for (int mt = 0; mt < MT; mt++) {
        int rbase = row0 + warp_m * (MT * 16) + mt * 16 + grp;
#pragma unroll
        for (int nt = 0; nt < 4; nt++) {
            int cb = col0 + warp_n * 32 + nt * 8 + 2 * qid;
#pragma unroll
            for (int half = 0; half < 2; half++) {
                int r = rbase + half * 8;
                if (r >= M) continue;
                float v0 = acc[mt][nt][half * 2 + 0];
                float v1 = acc[mt][nt][half * 2 + 1];
                if (EPI >= 1) { v0 += bias[cb]; v1 += bias[cb + 1]; }
                if (EPI == 1) {
                    v0 = v0 > 0.0f ? v0 : expm1f(v0);
                    v1 = v1 > 0.0f ? v1 : expm1f(v1);
                    *(__half2*)&Oh[(size_t)r * N + cb] = __floats2half2_rn(v0, v1);
                } else {
                    *(float2*)&C[(size_t)r * N + cb] = make_float2(v0, v1);
                }
            }
        }
    }
}

// ---------------- host orchestration ---------------------------------------
static inline int cdiv(long long a, long long b) { return (int)((a + b - 1) / b); }

extern "C" void kernel_launch(void* const* d_in, const int* in_sizes, int n_in,
                              void* d_out, int out_size) {
    const float* x    = (const float*)d_in[0];
    const int*   y    = (const int*)  d_in[1];
    const int*   adj  = (const int*)  d_in[3];
    const int*   idxl = (const int*)  d_in[4];
    const float* W0  = (const float*)d_in[6];
    const float* b0  = (const float*)d_in[7];
    const float* W1  = (const float*)d_in[8];
    const float* b1  = (const float*)d_in[9];
    const float* W2  = (const float*)d_in[10];
    const float* b2  = (const float*)d_in[11];
    const float* Wm0 = (const float*)d_in[12];
    const float* bm0 = (const float*)d_in[13];
    const float* Wm1 = (const float*)d_in[14];
    const float* bm1 = (const float*)d_in[15];

    int N = in_sizes[1];
    int E = in_sizes[3] / 2;
    int L = in_sizes[4];
    float* out = (float*)d_out;

    float* p_t;
    __half *p_hh, *p_mh, *p_xh;
    __half *w0h, *w0l, *w1h, *w1l, *w2h, *w2l, *wm0h, *wm0l, *wm1h, *wm1l;
    cudaGetSymbolAddress((void**)&p_t,  g_t);
    cudaGetSymbolAddress((void**)&p_hh, g_h_hi);
    cudaGetSymbolAddress((void**)&p_mh, g_m_hi);
    cudaGetSymbolAddress((void**)&p_xh, g_x_hi);
    cudaGetSymbolAddress((void**)&w0h,  g_w0t_hi);  cudaGetSymbolAddress((void**)&w0l,  g_w0t_lo);
    cudaGetSymbolAddress((void**)&w1h,  g_w1t_hi);  cudaGetSymbolAddress((void**)&w1l,  g_w1t_lo);
    cudaGetSymbolAddress((void**)&w2h,  g_w2t_hi);  cudaGetSymbolAddress((void**)&w2l,  g_w2t_lo);
    cudaGetSymbolAddress((void**)&wm0h, g_wm0t_hi); cudaGetSymbolAddress((void**)&wm0l, g_wm0t_lo);
    cudaGetSymbolAddress((void**)&wm1h, g_wm1t_hi); cudaGetSymbolAddress((void**)&wm1l, g_wm1t_lo);

    // lazy one-time stream/event creation (outside capture on the correctness call)
    static cudaStream_t s1 = nullptr;
    static cudaEvent_t evFork = nullptr, evJoin = nullptr;
    if (s1 == nullptr) {
        cudaStreamCreateWithFlags(&s1, cudaStreamNonBlocking);
        cudaEventCreateWithFlags(&evFork, cudaEventDisableTiming);
        cudaEventCreateWithFlags(&evJoin, cudaEventDisableTiming);
    }

    const int TB = 256;
    const int SMEM128 = 2 * 128 * 80 + 2 * 2 * 128 * 80;   // 61440
    const int SMEM64  = 2 * 128 * 80 + 2 * 2 * 64 * 80;    // 40960
    cudaFuncSetAttribute(k_hgemm<128, 0>, cudaFuncAttributeMaxDynamicSharedMemorySize, SMEM128);
    cudaFuncSetAttribute(k_hgemm<128, 1>, cudaFuncAttributeMaxDynamicSharedMemorySize, SMEM128);
    cudaFuncSetAttribute(k_hgemm<64, 2>,  cudaFuncAttributeMaxDynamicSharedMemorySize, SMEM64);

    long long xq = (long long)N * CNFEAT / 4;
    long long nwcell = (long long)N * 32;
    int gy = cdiv(N, 128);

    // ---- fork: prep branch on s1 runs concurrently with cast/wt0/GEMM1 ----
    cudaEventRecord(evFork, 0);
    cudaStreamWaitEvent(s1, evFork, 0);

    // stream 0: GEMM1 dependency chain
    k_cast16<<<cdiv(xq, TB), TB>>>(x, p_xh, xq);
    k_wt<<<cdiv(256 * 512, TB), TB>>>(W0, w0h, w0l, 512, 256);
    k_hgemm<128, 0><<<dim3(2, gy), 256, SMEM128>>>(p_xh, w0h, w0l,
                                                   p_t, nullptr, nullptr,
                                                   N, 256, 512);

    // stream s1: everything independent of GEMM1
    k_wt<<<cdiv(256 * 256, TB), TB, 0, s1>>>(W1, w1h, w1l, 256, 256);
    k_wt<<<cdiv(256 * 256, TB), TB, 0, s1>>>(W2, w2h, w2l, 256, 256);
    k_wt<<<cdiv(512 * 256, TB), TB, 0, s1>>>(Wm0, wm0h, wm0l, 256, 512);
    k_wt<<<cdiv(64 * 512, TB), TB, 0, s1>>>(Wm1, wm1h, wm1l, 512, 64);
    k_lab_init<<<cdiv(N, TB), TB, 0, s1>>>(N);
    k_lab_set<<<cdiv(L, TB), TB, 0, s1>>>(idxl, y, L);
    k_zero_cnt<<<cdiv(N, TB), TB, 0, s1>>>(N);
    k_count<<<cdiv(E, TB), TB, 0, s1>>>(adj, E);
    k_scan<<<1, 1024, 0, s1>>>(N, E);
    k_dinv<<<cdiv(N, TB), TB, 0, s1>>>(N);
    k_fill<<<cdiv(E, TB), TB, 0, s1>>>(adj, E);

    // ---- join ----
    cudaEventRecord(evJoin, s1);
    cudaStreamWaitEvent(0, evJoin, 0);

    // layer 1 finish
    k_lab_add<<<cdiv(nwcell, TB), TB>>>(W0, p_t, N);
    k_agg_csr<<<cdiv(nwcell, TB), TB>>>(p_t, p_hh, b0, N);

    // GCN layer 2
    k_hgemm<128, 0><<<dim3(2, gy), 256, SMEM128>>>(p_hh, w1h, w1l,
                                                   p_t, nullptr, nullptr,
                                                   N, 256, 256);
    k_agg_csr<<<cdiv(nwcell, TB), TB>>>(p_t, p_hh, b1, N);

    // GCN layer 3
    k_hgemm<128, 0><<<dim3(2, gy), 256, SMEM128>>>(p_hh, w2h, w2l,
                                                   p_t, nullptr, nullptr,
                                                   N, 256, 256);
    k_agg_csr<<<cdiv(nwcell, TB), TB>>>(p_t, p_hh, b2, N);

    // MLP head
    k_hgemm<128, 1><<<dim3(4, gy), 256, SMEM128>>>(p_hh, wm0h, wm0l,
                                                   nullptr, bm0, p_mh,
                                                   N, 512, 256);
    k_hgemm<64, 2><<<dim3(1, gy), 256, SMEM64>>>(p_mh, wm1h, wm1l,
                                                 out, bm1, nullptr,
                                                 N, 64, 512);

    // log_softmax
    k_logsoftmax64<<<cdiv(nwcell, TB), TB>>>(out, N);
}

// round 15
// speedup vs baseline: 1.4536x; 1.1681x over previous
#include <cuda_runtime.h>
#include <cuda_fp16.h>
#include <cstdint>
#include <math.h>

// Problem constants (fixed shapes)
#define CN      100000
#define CE      1600000
#define CNFEAT  512
#define CNLABEL 64
#define CNHID   256
#define CHID2   512

// ---------------- scratch (device globals) ----------------------------------
__device__ float  g_t   [(size_t)CN * CNHID];
__device__ __half g_h_hi[(size_t)CN * CNHID];
__device__ __half g_m_hi[(size_t)CN * CHID2];
__device__ __half g_x_hi[(size_t)CN * CNFEAT];
__device__ __half g_w0t[256 * 512];
__device__ __half g_w1t[256 * 256];
__device__ __half g_w2t[256 * 256];
__device__ __half g_wm0t[512 * 256];
__device__ __half g_wm1t[64 * 512];
__device__ float  g_dinv[CN];
__device__ int    g_cnt[CN];
__device__ int    g_rowptr[CN + 1];
__device__ int    g_cursor[CN];
__device__ int    g_src[CE];
__device__ float  g_w[CE];
__device__ int    g_lab[CN];

// ---------------- CSR build --------------------------------------------------
__global__ void k_zero_cnt(int n) {
    int i = blockIdx.x * blockDim.x + threadIdx.x;
    if (i < n) g_cnt[i] = 0;
}
__global__ void k_count(const int* __restrict__ adj, int E) {
    int e = blockIdx.x * blockDim.x + threadIdx.x;
    if (e >= E) return;
    atomicAdd(&g_cnt[adj[E + e]], 1);
}
__global__ void k_scan(int n, int E) {
    __shared__ int bs[1024];
    int tid = threadIdx.x;
    int chunk = (n + 1023) / 1024;
    int lo = tid * chunk;
    int hi = lo + chunk; if (hi > n) hi = n; if (lo > n) lo = n;
    int s = 0;
    for (int i = lo; i < hi; i++) s += g_cnt[i];
    int mysum = s;
    bs[tid] = s;
    __syncthreads();
    for (int d = 1; d < 1024; d <<= 1) {
        int v = (tid >= d) ? bs[tid - d] : 0;
        __syncthreads();
        bs[tid] += v;
        __syncthreads();
    }
    int off = bs[tid] - mysum;
    for (int i = lo; i < hi; i++) {
        g_rowptr[i] = off;
        g_cursor[i] = off;
        off += g_cnt[i];
    }
    if (tid == 1023) g_rowptr[n] = E;
}
__global__ void k_dinv(int n) {
    int i = blockIdx.x * blockDim.x + threadIdx.x;
    if (i < n) g_dinv[i] = rsqrtf((float)g_cnt[i] + 2.0f);
}
__global__ void k_fill(const int* __restrict__ adj, int E) {
    int e = blockIdx.x * blockDim.x + threadIdx.x;
    if (e >= E) return;
    int src = adj[e];
    int dst = adj[E + e];
    int pos = atomicAdd(&g_cursor[dst], 1);
    g_src[pos] = src;
    g_w[pos] = g_dinv[src] * g_dinv[dst];
}

// ---------------- labels ------------------------------------------------------
__global__ void k_lab_init(int n) {
    int i = blockIdx.x * blockDim.x + threadIdx.x;
    if (i < n) g_lab[i] = -1;
}
__global__ void k_lab_set(const int* __restrict__ idxl, const int* __restrict__ y, int L) {
    int t = blockIdx.x * blockDim.x + threadIdx.x;
    if (t >= L) return;
    int node = idxl[t];
    g_lab[node] = y[node];
}
__global__ void k_lab_add(const float* __restrict__ W0, float* __restrict__ t, int n) {
    int gt = blockIdx.x * blockDim.x + threadIdx.x;
    int warp = gt >> 5, lane = gt & 31;
    if (warp >= n) return;
    int lab = g_lab[warp];
    if (lab < 0) return;
    const float* wrow = W0 + (size_t)(CNFEAT + lab) * CNHID;
    float* trow = t + (size_t)warp * CNHID;
#pragma unroll
    for (int k = 0; k < CNHID / 32; k++)
        trow[k * 32 + lane] += wrow[k * 32 + lane];
}

// ---------------- cast / transpose helpers -------------------------------------
__global__ void k_cast16(const float* __restrict__ X, __half* __restrict__ H, long long nq) {
    long long i = (long long)blockIdx.x * blockDim.x + threadIdx.x;
    if (i >= nq) return;
    float4 v = ((const float4*)X)[i];
    ((__half2*)H)[2 * i]     = __floats2half2_rn(v.x, v.y);
    ((__half2*)H)[2 * i + 1] = __floats2half2_rn(v.z, v.w);
}

// weights: transpose + fp16 cast
__global__ void k_wt(const float* __restrict__ W, __half* __restrict__ TH, int K, int N) {
    int idx = blockIdx.x * blockDim.x + threadIdx.x;
    if (idx >= N * K) return;
    int n = idx / K, k = idx % K;
    TH[idx] = __float2half_rn(W[(size_t)k * N + n]);
}

// ---------------- fused CSR aggregation --------------------------------------
__global__ void __launch_bounds__(256)
k_agg_csr(const float* __restrict__ t, __half* __restrict__ Oh,
          const float* __restrict__ bias, int n) {
    int warp = (blockIdx.x * blockDim.x + threadIdx.x) >> 5;
    int lane = threadIdx.x & 31;
    if (warp >= n) return;
    int beg = g_rowptr[warp];
    int end = g_rowptr[warp + 1];
    const float4* ti = (const float4*)(t + (size_t)warp * CNHID);
    const float4* bi = (const float4*)bias;
    float d = g_dinv[warp];
    float sw = 2.0f * d * d;

    float4 a0 = bi[lane], a1 = bi[32 + lane];
    float4 s0 = ti[lane], s1 = ti[32 + lane];
    a0.x += sw * s0.x; a0.y += sw * s0.y; a0.z += sw * s0.z; a0.w += sw * s0.w;
    a1.x += sw * s1.x; a1.y += sw * s1.y; a1.z += sw * s1.z; a1.w += sw * s1.w;

    int e = beg;
    for (; e + 1 < end; e += 2) {
        int sA = g_src[e], sB = g_src[e + 1];
        float wA = g_w[e], wB = g_w[e + 1];
        const float4* tA = (const float4*)(t + (size_t)sA * CNHID);
        const float4* tB = (const float4*)(t + (size_t)sB * CNHID);
        float4 vA0 = tA[lane], vA1 = tA[32 + lane];
        float4 vB0 = tB[lane], vB1 = tB[32 + lane];
        a0.x = fmaf(wA, vA0.x, a0.x); a0.y = fmaf(wA, vA0.y, a0.y);
        a0.z = fmaf(wA, vA0.z, a0.z); a0.w = fmaf(wA, vA0.w, a0.w);
        a1.x = fmaf(wA, vA1.x, a1.x); a1.y = fmaf(wA, vA1.y, a1.y);
        a1.z = fmaf(wA, vA1.z, a1.z); a1.w = fmaf(wA, vA1.w, a1.w);
        a0.x = fmaf(wB, vB0.x, a0.x); a0.y = fmaf(wB, vB0.y, a0.y);
        a0.z = fmaf(wB, vB0.z, a0.z); a0.w = fmaf(wB, vB0.w, a0.w);
        a1.x = fmaf(wB, vB1.x, a1.x); a1.y = fmaf(wB, vB1.y, a1.y);
        a1.z = fmaf(wB, vB1.z, a1.z); a1.w = fmaf(wB, vB1.w, a1.w);
    }
    if (e < end) {
        int sA = g_src[e];
        float wA = g_w[e];
        const float4* tA = (const float4*)(t + (size_t)sA * CNHID);
        float4 vA0 = tA[lane], vA1 = tA[32 + lane];
        a0.x = fmaf(wA, vA0.x, a0.x); a0.y = fmaf(wA, vA0.y, a0.y);
        a0.z = fmaf(wA, vA0.z, a0.z); a0.w = fmaf(wA, vA0.w, a0.w);
        a1.x = fmaf(wA, vA1.x, a1.x); a1.y = fmaf(wA, vA1.y, a1.y);
        a1.z = fmaf(wA, vA1.z, a1.z); a1.w = fmaf(wA, vA1.w, a1.w);
    }

    __half2 o0 = __floats2half2_rn(fmaxf(a0.x, 0.f), fmaxf(a0.y, 0.f));
    __half2 o1 = __floats2half2_rn(fmaxf(a0.z, 0.f), fmaxf(a0.w, 0.f));
    __half2 o2 = __floats2half2_rn(fmaxf(a1.x, 0.f), fmaxf(a1.y, 0.f));
    __half2 o3 = __floats2half2_rn(fmaxf(a1.z, 0.f), fmaxf(a1.w, 0.f));
    size_t base = (size_t)warp * CNHID + 4 * lane;
    __half2* hp = (__half2*)&Oh[base];
    hp[0] = o0; hp[1] = o1;
    __half2* hp2 = (__half2*)&Oh[base + 128];
    hp2[0] = o2; hp2[1] = o3;
}

// ---------------- log_softmax --------------------------------------------------
__global__ void k_logsoftmax64(float* __restrict__ out, int n) {
    int gt = blockIdx.x * blockDim.x + threadIdx.x;
    int warp = gt >> 5, lane = gt & 31;
    if (warp >= n) return;
    float* r = out + (size_t)warp * 64;
    float v0 = r[lane], v1 = r[lane + 32];
    float m = fmaxf(v0, v1);
#pragma unroll
    for (int o = 16; o; o >>= 1) m = fmaxf(m, __shfl_xor_sync(0xffffffffu, m, o));
    float s = expf(v0 - m) + expf(v1 - m);
#pragma unroll
    for (int o = 16; o; o >>= 1) s += __shfl_xor_sync(0xffffffffu, s, o);
    float l = m + logf(s);
    r[lane] = v0 - l;
    r[lane + 32] = v1 - l;
}

// ---------------- 1-term FP16 tensor-core GEMM ---------------------------------
__device__ __forceinline__ void mma_f16(float* c, const uint32_t* a, const uint32_t* b) {
    asm volatile(
        "mma.sync.aligned.m16n8k16.row.col.f32.f16.f16.f32 "
        "{%0,%1,%2,%3}, {%4,%5,%6,%7}, {%8,%9}, {%0,%1,%2,%3};\n"
        : "+f"(c[0]), "+f"(c[1]), "+f"(c[2]), "+f"(c[3])
        : "r"(a[0]), "r"(a[1]), "r"(a[2]), "r"(a[3]), "r"(b[0]), "r"(b[1]));
}
__device__ __forceinline__ void ldsm4(uint32_t& r0, uint32_t& r1, uint32_t& r2,
                                      uint32_t& r3, uint32_t addr) {
    asm volatile("ldmatrix.sync.aligned.m8n8.x4.shared.b16 {%0,%1,%2,%3}, [%4];"
                 : "=r"(r0), "=r"(r1), "=r"(r2), "=r"(r3) : "r"(addr));
}
__device__ __forceinline__ uint32_t s2u(const void* p) {
    uint32_t a;
    asm("{ .reg .u64 t; cvta.to.shared.u64 t, %1; cvt.u32.u64 %0, t; }" : "=r"(a) : "l"(p));
    return a;
}
__device__ __forceinline__ void cpa16(uint32_t dst, const void* src, bool pred) {
    asm volatile("cp.async.cg.shared.global [%0], [%1], 16, %2;"
                 :: "r"(dst), "l"(src), "r"(pred ? 16 : 0) : "memory");
}
__device__ __forceinline__ void cpa_commit() {
    asm volatile("cp.async.commit_group;" ::: "memory");
}
__device__ __forceinline__ void cpa_wait0() {
    asm volatile("cp.async.wait_group 0;" ::: "memory");
}

// C[M,N] = A_hi @ B_hi; A f16 [M][K]; B transposed f16 [N][K]. BM=128, BK=32.
// EPI: 0 plain fp32 | 1 bias+ELU -> fp16 Oh | 2 bias fp32
template <int BN, int EPI>
__global__ void __launch_bounds__(256)
k_hgemm(const __half* __restrict__ Ah,
        const __half* __restrict__ Bh,
        float* __restrict__ C, const float* __restrict__ bias,
        __half* __restrict__ Oh,
        int M, int N, int K) {
    constexpr int RSTR  = 80;                 // 64B data + 16B pad
    constexpr int ATILE = 128 * RSTR;
    constexpr int BTILE = BN * RSTR;
    constexpr int OFFB  = 2 * ATILE;
    constexpr int NWN   = BN / 32;
    constexpr int MT    = (128 / (8 / NWN)) / 16;

    extern __shared__ char smem[];
    const uint32_t sb = s2u(smem);
    const int tid = threadIdx.x;
    const int wid = tid >> 5, lane = tid & 31;
    const int grp = lane >> 2, qid = lane & 3;
    const int warp_m = wid / NWN, warp_n = wid % NWN;
    const int row0 = blockIdx.y * 128;
    const int col0 = blockIdx.x * BN;

    const int lrow = lane & 15;
    const int lcol = (lane >> 4) * 16;

    float acc[MT][4][4];
#pragma unroll
    for (int i = 0; i < MT; i++)
#pragma unroll
        for (int j = 0; j < 4; j++)
#pragma unroll
            for (int c = 0; c < 4; c++) acc[i][j][c] = 0.0f;

    auto loadSlab = [&](int s, int b) {
        int k0 = s * 32;
#pragma unroll
        for (int i = 0; i < 2; i++) {
            int c = tid + i * 256;
            int r = c >> 2, p = c & 3;
            bool ok = (row0 + r) < M;
            int rr = ok ? (row0 + r) : (M - 1);
            size_t g = (size_t)rr * K + k0 + p * 8;
            cpa16(sb + b * ATILE + r * RSTR + p * 16, Ah + g, ok);
        }
#pragma unroll
        for (int i = 0; i < BN / 64; i++) {
            int c = tid + i * 256;
            int r = c >> 2, p = c & 3;
            size_t g = (size_t)(col0 + r) * K + k0 + p * 8;
            cpa16(sb + OFFB + b * BTILE + r * RSTR + p * 16, Bh + g, true);
        }
        cpa_commit();
    };

    auto computeSlab = [&](int b) {
        const uint32_t aB = sb + b * ATILE;
        const uint32_t bB = sb + OFFB + b * BTILE;
#pragma unroll
        for (int ks = 0; ks < 2; ks++) {
            const int kb = ks * 32 + lcol;
            uint32_t bh[4][2];
#pragma unroll
            for (int p = 0; p < 2; p++) {
                uint32_t addr = bB + (warp_n * 32 + p * 16 + lrow) * RSTR + kb;
                ldsm4(bh[2 * p][0], bh[2 * p + 1][0], bh[2 * p][1], bh[2 * p + 1][1], addr);
            }
#pragma unroll
            for (int mt = 0; mt < MT; mt++) {
                uint32_t addr = aB + (warp_m * (MT * 16) + mt * 16 + lrow) * RSTR + kb;
                uint32_t ah[4];
                ldsm4(ah[0], ah[1], ah[2], ah[3], addr);
#pragma unroll
                for (int nt = 0; nt < 4; nt++)
                    mma_f16(acc[mt][nt], ah, bh[nt]);
            }
        }
    };

    const int ns = K / 32;
    loadSlab(0, 0);
    cpa_wait0();
    __syncthreads();
    for (int s = 0; s < ns; s++) {
        int b = s & 1;
        if (s + 1 < ns) loadSlab(s + 1, b ^ 1);
        computeSlab(b);
        if (s + 1 < ns) {
            cpa_wait0();
            __syncthreads();
        }
    }

    // ---- epilogue ----
#pragma unroll
    for (int mt = 0; mt < MT; mt++) {
        int rbase = row0 + warp_m * (MT * 16) + mt * 16 + grp;
#pragma unroll
        for (int nt = 0; nt < 4; nt++) {
            int cb = col0 + warp_n * 32 + nt * 8 + 2 * qid;
#pragma unroll
            for (int half = 0; half < 2; half++) {
                int r = rbase + half * 8;
                if (r >= M) continue;
                float v0 = acc[mt][nt][half * 2 + 0];
                float v1 = acc[mt][nt][half * 2 + 1];
                if (EPI >= 1) { v0 += bias[cb]; v1 += bias[cb + 1]; }
                if (EPI == 1) {
                    v0 = v0 > 0.0f ? v0 : expm1f(v0);
                    v1 = v1 > 0.0f ? v1 : expm1f(v1);
                    *(__half2*)&Oh[(size_t)r * N + cb] = __floats2half2_rn(v0, v1);
                } else {
                    *(float2*)&C[(size_t)r * N + cb] = make_float2(v0, v1);
                }
            }
        }
    }
}

// ---------------- host orchestration ---------------------------------------
static inline int cdiv(long long a, long long b) { return (int)((a + b - 1) / b); }

extern "C" void kernel_launch(void* const* d_in, const int* in_sizes, int n_in,
                              void* d_out, int out_size) {
    const float* x    = (const float*)d_in[0];
    const int*   y    = (const int*)  d_in[1];
    const int*   adj  = (const int*)  d_in[3];
    const int*   idxl = (const int*)  d_in[4];
    const float* W0  = (const float*)d_in[6];
    const float* b0  = (const float*)d_in[7];
    const float* W1  = (const float*)d_in[8];
    const float* b1  = (const float*)d_in[9];
    const float* W2  = (const float*)d_in[10];
    const float* b2  = (const float*)d_in[11];
    const float* Wm0 = (const float*)d_in[12];
    const float* bm0 = (const float*)d_in[13];
    const float* Wm1 = (const float*)d_in[14];
    const float* bm1 = (const float*)d_in[15];

    int N = in_sizes[1];
    int E = in_sizes[3] / 2;
    int L = in_sizes[4];
    float* out = (float*)d_out;

    float* p_t;
    __half *p_hh, *p_mh, *p_xh;
    __half *w0t, *w1t, *w2t, *wm0t, *wm1t;
    cudaGetSymbolAddress((void**)&p_t,  g_t);
    cudaGetSymbolAddress((void**)&p_hh, g_h_hi);
    cudaGetSymbolAddress((void**)&p_mh, g_m_hi);
    cudaGetSymbolAddress((void**)&p_xh, g_x_hi);
    cudaGetSymbolAddress((void**)&w0t,  g_w0t);
    cudaGetSymbolAddress((void**)&w1t,  g_w1t);
    cudaGetSymbolAddress((void**)&w2t,  g_w2t);
    cudaGetSymbolAddress((void**)&wm0t, g_wm0t);
    cudaGetSymbolAddress((void**)&wm1t, g_wm1t);

    // lazy one-time stream/event creation (outside capture on the correctness call)
    static cudaStream_t s1 = nullptr;
    static cudaEvent_t evFork = nullptr, evJoin = nullptr;
    if (s1 == nullptr) {
        cudaStreamCreateWithFlags(&s1, cudaStreamNonBlocking);
        cudaEventCreateWithFlags(&evFork, cudaEventDisableTiming);
        cudaEventCreateWithFlags(&evJoin, cudaEventDisableTiming);
    }

    const int TB = 256;
    const int SMEM128 = 2 * 128 * 80 + 2 * 128 * 80;   // 40960
    const int SMEM64  = 2 * 128 * 80 + 2 * 64 * 80;    // 30720
    cudaFuncSetAttribute(k_hgemm<128, 0>, cudaFuncAttributeMaxDynamicSharedMemorySize, SMEM128);
    cudaFuncSetAttribute(k_hgemm<128, 1>, cudaFuncAttributeMaxDynamicSharedMemorySize, SMEM128);
    cudaFuncSetAttribute(k_hgemm<64, 2>,  cudaFuncAttributeMaxDynamicSharedMemorySize, SMEM64);

    long long xq = (long long)N * CNFEAT / 4;
    long long nwcell = (long long)N * 32;
    int gy = cdiv(N, 128);

    // ---- fork: prep branch on s1 runs concurrently with cast/wt0/GEMM1 ----
    cudaEventRecord(evFork, 0);
    cudaStreamWaitEvent(s1, evFork, 0);

    // stream 0: GEMM1 dependency chain
    k_cast16<<<cdiv(xq, TB), TB>>>(x, p_xh, xq);
    k_wt<<<cdiv(256 * 512, TB), TB>>>(W0, w0t, 512, 256);
    k_hgemm<128, 0><<<dim3(2, gy), 256, SMEM128>>>(p_xh, w0t,
                                                   p_t, nullptr, nullptr,
                                                   N, 256, 512);

    // stream s1: everything independent of GEMM1
    k_wt<<<cdiv(256 * 256, TB), TB, 0, s1>>>(W1, w1t, 256, 256);
    k_wt<<<cdiv(256 * 256, TB), TB, 0, s1>>>(W2, w2t, 256, 256);
    k_wt<<<cdiv(512 * 256, TB), TB, 0, s1>>>(Wm0, wm0t, 256, 512);
    k_wt<<<cdiv(64 * 512, TB), TB, 0, s1>>>(Wm1, wm1t, 512, 64);
    k_lab_init<<<cdiv(N, TB), TB, 0, s1>>>(N);
    k_lab_set<<<cdiv(L, TB), TB, 0, s1>>>(idxl, y, L);
    k_zero_cnt<<<cdiv(N, TB), TB, 0, s1>>>(N);
    k_count<<<cdiv(E, TB), TB, 0, s1>>>(adj, E);
    k_scan<<<1, 1024, 0, s1>>>(N, E);
    k_dinv<<<cdiv(N, TB), TB, 0, s1>>>(N);
    k_fill<<<cdiv(E, TB), TB, 0, s1>>>(adj, E);

    // ---- join ----
    cudaEventRecord(evJoin, s1);
    cudaStreamWaitEvent(0, evJoin, 0);

    // layer 1 finish
    k_lab_add<<<cdiv(nwcell, TB), TB>>>(W0, p_t, N);
    k_agg_csr<<<cdiv(nwcell, TB), TB>>>(p_t, p_hh, b0, N);

    // GCN layer 2
    k_hgemm<128, 0><<<dim3(2, gy), 256, SMEM128>>>(p_hh, w1t,
                                                   p_t, nullptr, nullptr,
                                                   N, 256, 256);
    k_agg_csr<<<cdiv(nwcell, TB), TB>>>(p_t, p_hh, b1, N);

    // GCN layer 3
    k_hgemm<128, 0><<<dim3(2, gy), 256, SMEM128>>>(p_hh, w2t,
                                                   p_t, nullptr, nullptr,
                                                   N, 256, 256);
    k_agg_csr<<<cdiv(nwcell, TB), TB>>>(p_t, p_hh, b2, N);

    // MLP head
    k_hgemm<128, 1><<<dim3(4, gy), 256, SMEM128>>>(p_hh, wm0t,
                                                   nullptr, bm0, p_mh,
                                                   N, 512, 256);
    k_hgemm<64, 2><<<dim3(1, gy), 256, SMEM64>>>(p_mh, wm1t,
                                                 out, bm1, nullptr,
                                                 N, 64, 512);

    // log_softmax
    k_logsoftmax64<<<cdiv(nwcell, TB), TB>>>(out, N);
}

// round 16
// speedup vs baseline: 1.6924x; 1.1643x over previous
#include <cuda_runtime.h>
#include <cuda_fp16.h>
#include <cstdint>
#include <math.h>

// Problem constants (fixed shapes)
#define CN      100000
#define CE      1600000
#define CNFEAT  512
#define CNLABEL 64
#define CNHID   256
#define CHID2   512

// ---------------- scratch (device globals) ----------------------------------
__device__ __half g_t16 [(size_t)CN * CNHID];   // GEMM output (fp16) for aggregation
__device__ __half g_h16 [(size_t)CN * CNHID];   // hidden state (fp16)
__device__ __half g_m16 [(size_t)CN * CHID2];   // MLP hidden (fp16)
__device__ __half g_x16 [(size_t)CN * CNFEAT];  // input features (fp16)
__device__ __half g_w0t[256 * 512];
__device__ __half g_w1t[256 * 256];
__device__ __half g_w2t[256 * 256];
__device__ __half g_wm0t[512 * 256];
__device__ __half g_wm1t[64 * 512];
__device__ float  g_dinv[CN];
__device__ int    g_cnt[CN];
__device__ int    g_rowptr[CN + 1];
__device__ int    g_cursor[CN];
__device__ int    g_src[CE];
__device__ float  g_w[CE];
__device__ int    g_lab[CN];

// ---------------- CSR build --------------------------------------------------
__global__ void k_zero_cnt(int n) {
    int i = blockIdx.x * blockDim.x + threadIdx.x;
    if (i < n) g_cnt[i] = 0;
}
__global__ void k_count(const int* __restrict__ adj, int E) {
    int e = blockIdx.x * blockDim.x + threadIdx.x;
    if (e >= E) return;
    atomicAdd(&g_cnt[adj[E + e]], 1);
}
__global__ void k_scan(int n, int E) {
    __shared__ int bs[1024];
    int tid = threadIdx.x;
    int chunk = (n + 1023) / 1024;
    int lo = tid * chunk;
    int hi = lo + chunk; if (hi > n) hi = n; if (lo > n) lo = n;
    int s = 0;
    for (int i = lo; i < hi; i++) s += g_cnt[i];
    int mysum = s;
    bs[tid] = s;
    __syncthreads();
    for (int d = 1; d < 1024; d <<= 1) {
        int v = (tid >= d) ? bs[tid - d] : 0;
        __syncthreads();
        bs[tid] += v;
        __syncthreads();
    }
    int off = bs[tid] - mysum;
    for (int i = lo; i < hi; i++) {
        g_rowptr[i] = off;
        g_cursor[i] = off;
        off += g_cnt[i];
    }
    if (tid == 1023) g_rowptr[n] = E;
}
__global__ void k_dinv(int n) {
    int i = blockIdx.x * blockDim.x + threadIdx.x;
    if (i < n) g_dinv[i] = rsqrtf((float)g_cnt[i] + 2.0f);
}
__global__ void k_fill(const int* __restrict__ adj, int E) {
    int e = blockIdx.x * blockDim.x + threadIdx.x;
    if (e >= E) return;
    int src = adj[e];
    int dst = adj[E + e];
    int pos = atomicAdd(&g_cursor[dst], 1);
    g_src[pos] = src;
    g_w[pos] = g_dinv[src] * g_dinv[dst];
}

// ---------------- labels ------------------------------------------------------
__global__ void k_lab_init(int n) {
    int i = blockIdx.x * blockDim.x + threadIdx.x;
    if (i < n) g_lab[i] = -1;
}
__global__ void k_lab_set(const int* __restrict__ idxl, const int* __restrict__ y, int L) {
    int t = blockIdx.x * blockDim.x + threadIdx.x;
    if (t >= L) return;
    int node = idxl[t];
    g_lab[node] = y[node];
}
// t16[node,:] += W0[512+lab, :]  (fp16 t)
__global__ void k_lab_add(const float* __restrict__ W0, __half* __restrict__ t, int n) {
    int gt = blockIdx.x * blockDim.x + threadIdx.x;
    int warp = gt >> 5, lane = gt & 31;
    if (warp >= n) return;
    int lab = g_lab[warp];
    if (lab < 0) return;
    const float* wrow = W0 + (size_t)(CNFEAT + lab) * CNHID;
    __half* trow = t + (size_t)warp * CNHID;
#pragma unroll
    for (int k = 0; k < CNHID / 32; k++) {
        int i = k * 32 + lane;
        trow[i] = __float2half_rn(__half2float(trow[i]) + wrow[i]);
    }
}

// ---------------- cast / transpose helpers -------------------------------------
__global__ void k_cast16(const float* __restrict__ X, __half* __restrict__ H, long long nq) {
    long long i = (long long)blockIdx.x * blockDim.x + threadIdx.x;
    if (i >= nq) return;
    float4 v = ((const float4*)X)[i];
    ((__half2*)H)[2 * i]     = __floats2half2_rn(v.x, v.y);
    ((__half2*)H)[2 * i + 1] = __floats2half2_rn(v.z, v.w);
}

__global__ void k_wt(const float* __restrict__ W, __half* __restrict__ TH, int K, int N) {
    int idx = blockIdx.x * blockDim.x + threadIdx.x;
    if (idx >= N * K) return;
    int n = idx / K, k = idx % K;
    TH[idx] = __float2half_rn(W[(size_t)k * N + n]);
}

// ---------------- fused CSR aggregation (fp16 gathers) -------------------------
__device__ __forceinline__ void h8acc(uint4 v, float w, float* a) {
    const __half2* h = (const __half2*)&v;
    float2 f0 = __half22float2(h[0]);
    float2 f1 = __half22float2(h[1]);
    float2 f2 = __half22float2(h[2]);
    float2 f3 = __half22float2(h[3]);
    a[0] = fmaf(w, f0.x, a[0]); a[1] = fmaf(w, f0.y, a[1]);
    a[2] = fmaf(w, f1.x, a[2]); a[3] = fmaf(w, f1.y, a[3]);
    a[4] = fmaf(w, f2.x, a[4]); a[5] = fmaf(w, f2.y, a[5]);
    a[6] = fmaf(w, f3.x, a[6]); a[7] = fmaf(w, f3.y, a[7]);
}

__global__ void __launch_bounds__(256)
k_agg_csr(const __half* __restrict__ t, __half* __restrict__ Oh,
          const float* __restrict__ bias, int n) {
    int warp = (blockIdx.x * blockDim.x + threadIdx.x) >> 5;
    int lane = threadIdx.x & 31;
    if (warp >= n) return;
    int beg = g_rowptr[warp];
    int end = g_rowptr[warp + 1];

    float acc[8];
    {
        float4 b0 = ((const float4*)bias)[2 * lane];
        float4 b1 = ((const float4*)bias)[2 * lane + 1];
        acc[0] = b0.x; acc[1] = b0.y; acc[2] = b0.z; acc[3] = b0.w;
        acc[4] = b1.x; acc[5] = b1.y; acc[6] = b1.z; acc[7] = b1.w;
    }
    // self-loop term
    {
        float d = g_dinv[warp];
        float sw = 2.0f * d * d;
        uint4 sv = ((const uint4*)(t + (size_t)warp * CNHID))[lane];
        h8acc(sv, sw, acc);
    }

    int e = beg;
    for (; e + 1 < end; e += 2) {
        int sA = g_src[e], sB = g_src[e + 1];
        float wA = g_w[e], wB = g_w[e + 1];
        uint4 vA = ((const uint4*)(t + (size_t)sA * CNHID))[lane];
        uint4 vB = ((const uint4*)(t + (size_t)sB * CNHID))[lane];
        h8acc(vA, wA, acc);
        h8acc(vB, wB, acc);
    }
    if (e < end) {
        int sA = g_src[e];
        float wA = g_w[e];
        uint4 vA = ((const uint4*)(t + (size_t)sA * CNHID))[lane];
        h8acc(vA, wA, acc);
    }

    // relu + fp16 pack
    uint4 ov;
    __half2* oh = (__half2*)&ov;
    oh[0] = __floats2half2_rn(fmaxf(acc[0], 0.f), fmaxf(acc[1], 0.f));
    oh[1] = __floats2half2_rn(fmaxf(acc[2], 0.f), fmaxf(acc[3], 0.f));
    oh[2] = __floats2half2_rn(fmaxf(acc[4], 0.f), fmaxf(acc[5], 0.f));
    oh[3] = __floats2half2_rn(fmaxf(acc[6], 0.f), fmaxf(acc[7], 0.f));
    ((uint4*)(Oh + (size_t)warp * CNHID))[lane] = ov;
}

// ---------------- log_softmax --------------------------------------------------
__global__ void k_logsoftmax64(float* __restrict__ out, int n) {
    int gt = blockIdx.x * blockDim.x + threadIdx.x;
    int warp = gt >> 5, lane = gt & 31;
    if (warp >= n) return;
    float* r = out + (size_t)warp * 64;
    float v0 = r[lane], v1 = r[lane + 32];
    float m = fmaxf(v0, v1);
#pragma unroll
    for (int o = 16; o; o >>= 1) m = fmaxf(m, __shfl_xor_sync(0xffffffffu, m, o));
    float s = expf(v0 - m) + expf(v1 - m);
#pragma unroll
    for (int o = 16; o; o >>= 1) s += __shfl_xor_sync(0xffffffffu, s, o);
    float l = m + logf(s);
    r[lane] = v0 - l;
    r[lane + 32] = v1 - l;
}

// ---------------- 1-term FP16 tensor-core GEMM ---------------------------------
__device__ __forceinline__ void mma_f16(float* c, const uint32_t* a, const uint32_t* b) {
    asm volatile(
        "mma.sync.aligned.m16n8k16.row.col.f32.f16.f16.f32 "
        "{%0,%1,%2,%3}, {%4,%5,%6,%7}, {%8,%9}, {%0,%1,%2,%3};\n"
        : "+f"(c[0]), "+f"(c[1]), "+f"(c[2]), "+f"(c[3])
        : "r"(a[0]), "r"(a[1]), "r"(a[2]), "r"(a[3]), "r"(b[0]), "r"(b[1]));
}
__device__ __forceinline__ void ldsm4(uint32_t& r0, uint32_t& r1, uint32_t& r2,
                                      uint32_t& r3, uint32_t addr) {
    asm volatile("ldmatrix.sync.aligned.m8n8.x4.shared.b16 {%0,%1,%2,%3}, [%4];"
                 : "=r"(r0), "=r"(r1), "=r"(r2), "=r"(r3) : "r"(addr));
}
__device__ __forceinline__ uint32_t s2u(const void* p) {
    uint32_t a;
    asm("{ .reg .u64 t; cvta.to.shared.u64 t, %1; cvt.u32.u64 %0, t; }" : "=r"(a) : "l"(p));
    return a;
}
__device__ __forceinline__ void cpa16(uint32_t dst, const void* src, bool pred) {
    asm volatile("cp.async.cg.shared.global [%0], [%1], 16, %2;"
                 :: "r"(dst), "l"(src), "r"(pred ? 16 : 0) : "memory");
}
__device__ __forceinline__ void cpa_commit() {
    asm volatile("cp.async.commit_group;" ::: "memory");
}
__device__ __forceinline__ void cpa_wait0() {
    asm volatile("cp.async.wait_group 0;" ::: "memory");
}

// C[M,N] = A @ B; A f16 [M][K]; B transposed f16 [N][K]. BM=128, BK=32.
// EPI: 0 plain -> fp16 Oh | 1 bias+ELU -> fp16 Oh | 2 bias -> fp32 C
template <int BN, int EPI>
__global__ void __launch_bounds__(256)
k_hgemm(const __half* __restrict__ Ah,
        const __half* __restrict__ Bh,
        float* __restrict__ C, const float* __restrict__ bias,
        __half* __restrict__ Oh,
        int M, int N, int K) {
    constexpr int RSTR  = 80;                 // 64B data + 16B pad
    constexpr int ATILE = 128 * RSTR;
    constexpr int BTILE = BN * RSTR;
    constexpr int OFFB  = 2 * ATILE;
    constexpr int NWN   = BN / 32;
    constexpr int MT    = (128 / (8 / NWN)) / 16;

    extern __shared__ char smem[];
    const uint32_t sb = s2u(smem);
    const int tid = threadIdx.x;
    const int wid = tid >> 5, lane = tid & 31;
    const int grp = lane >> 2, qid = lane & 3;
    const int warp_m = wid / NWN, warp_n = wid % NWN;
    const int row0 = blockIdx.y * 128;
    const int col0 = blockIdx.x * BN;

    const int lrow = lane & 15;
    const int lcol = (lane >> 4) * 16;

    float acc[MT][4][4];
#pragma unroll
    for (int i = 0; i < MT; i++)
#pragma unroll
        for (int j = 0; j < 4; j++)
#pragma unroll
            for (int c = 0; c < 4; c++) acc[i][j][c] = 0.0f;

    auto loadSlab = [&](int s, int b) {
        int k0 = s * 32;
#pragma unroll
        for (int i = 0; i < 2; i++) {
            int c = tid + i * 256;
            int r = c >> 2, p = c & 3;
            bool ok = (row0 + r) < M;
            int rr = ok ? (row0 + r) : (M - 1);
            size_t g = (size_t)rr * K + k0 + p * 8;
            cpa16(sb + b * ATILE + r * RSTR + p * 16, Ah + g, ok);
        }
#pragma unroll
        for (int i = 0; i < BN / 64; i++) {
            int c = tid + i * 256;
            int r = c >> 2, p = c & 3;
            size_t g = (size_t)(col0 + r) * K + k0 + p * 8;
            cpa16(sb + OFFB + b * BTILE + r * RSTR + p * 16, Bh + g, true);
        }
        cpa_commit();
    };

    auto computeSlab = [&](int b) {
        const uint32_t aB = sb + b * ATILE;
        const uint32_t bB = sb + OFFB + b * BTILE;
#pragma unroll
        for (int ks = 0; ks < 2; ks++) {
            const int kb = ks * 32 + lcol;
            uint32_t bh[4][2];
#pragma unroll
            for (int p = 0; p < 2; p++) {
                uint32_t addr = bB + (warp_n * 32 + p * 16 + lrow) * RSTR + kb;
                ldsm4(bh[2 * p][0], bh[2 * p + 1][0], bh[2 * p][1], bh[2 * p + 1][1], addr);
            }
#pragma unroll
            for (int mt = 0; mt < MT; mt++) {
                uint32_t addr = aB + (warp_m * (MT * 16) + mt * 16 + lrow) * RSTR + kb;
                uint32_t ah[4];
                ldsm4(ah[0], ah[1], ah[2], ah[3], addr);
#pragma unroll
                for (int nt = 0; nt < 4; nt++)
                    mma_f16(acc[mt][nt], ah, bh[nt]);
            }
        }
    };

    const int ns = K / 32;
    loadSlab(0, 0);
    cpa_wait0();
    __syncthreads();
    for (int s = 0; s < ns; s++) {
        int b = s & 1;
        if (s + 1 < ns) loadSlab(s + 1, b ^ 1);
        computeSlab(b);
        if (s + 1 < ns) {
            cpa_wait0();
            __syncthreads();
        }
    }

    // ---- epilogue ----
#pragma unroll
    for (int mt = 0; mt < MT; mt++) {
        int rbase = row0 + warp_m * (MT * 16) + mt * 16 + grp;
#pragma unroll
        for (int nt = 0; nt < 4; nt++) {
            int cb = col0 + warp_n * 32 + nt * 8 + 2 * qid;
#pragma unroll
            for (int half = 0; half < 2; half++) {
                int r = rbase + half * 8;
                if (r >= M) continue;
                float v0 = acc[mt][nt][half * 2 + 0];
                float v1 = acc[mt][nt][half * 2 + 1];
                if (EPI >= 1) { v0 += bias[cb]; v1 += bias[cb + 1]; }
                if (EPI == 1) {
                    v0 = v0 > 0.0f ? v0 : expm1f(v0);
                    v1 = v1 > 0.0f ? v1 : expm1f(v1);
                }
                if (EPI == 2) {
                    *(float2*)&C[(size_t)r * N + cb] = make_float2(v0, v1);
                } else {
                    *(__half2*)&Oh[(size_t)r * N + cb] = __floats2half2_rn(v0, v1);
                }
            }
        }
    }
}

// ---------------- host orchestration ---------------------------------------
static inline int cdiv(long long a, long long b) { return (int)((a + b - 1) / b); }

extern "C" void kernel_launch(void* const* d_in, const int* in_sizes, int n_in,
                              void* d_out, int out_size) {
    const float* x    = (const float*)d_in[0];
    const int*   y    = (const int*)  d_in[1];
    const int*   adj  = (const int*)  d_in[3];
    const int*   idxl = (const int*)  d_in[4];
    const float* W0  = (const float*)d_in[6];
    const float* b0  = (const float*)d_in[7];
    const float* W1  = (const float*)d_in[8];
    const float* b1  = (const float*)d_in[9];
    const float* W2  = (const float*)d_in[10];
    const float* b2  = (const float*)d_in[11];
    const float* Wm0 = (const float*)d_in[12];
    const float* bm0 = (const float*)d_in[13];
    const float* Wm1 = (const float*)d_in[14];
    const float* bm1 = (const float*)d_in[15];

    int N = in_sizes[1];
    int E = in_sizes[3] / 2;
    int L = in_sizes[4];
    float* out = (float*)d_out;

    __half *p_t, *p_h, *p_m, *p_x;
    __half *w0t, *w1t, *w2t, *wm0t, *wm1t;
    cudaGetSymbolAddress((void**)&p_t, g_t16);
    cudaGetSymbolAddress((void**)&p_h, g_h16);
    cudaGetSymbolAddress((void**)&p_m, g_m16);
    cudaGetSymbolAddress((void**)&p_x, g_x16);
    cudaGetSymbolAddress((void**)&w0t,  g_w0t);
    cudaGetSymbolAddress((void**)&w1t,  g_w1t);
    cudaGetSymbolAddress((void**)&w2t,  g_w2t);
    cudaGetSymbolAddress((void**)&wm0t, g_wm0t);
    cudaGetSymbolAddress((void**)&wm1t, g_wm1t);

    // lazy one-time stream/event creation (outside capture on the correctness call)
    static cudaStream_t s1 = nullptr;
    static cudaEvent_t evFork = nullptr, evJoin = nullptr;
    if (s1 == nullptr) {
        cudaStreamCreateWithFlags(&s1, cudaStreamNonBlocking);
        cudaEventCreateWithFlags(&evFork, cudaEventDisableTiming);
        cudaEventCreateWithFlags(&evJoin, cudaEventDisableTiming);
    }

    const int TB = 256;
    const int SMEM128 = 2 * 128 * 80 + 2 * 128 * 80;   // 40960
    const int SMEM64  = 2 * 128 * 80 + 2 * 64 * 80;    // 30720
    cudaFuncSetAttribute(k_hgemm<128, 0>, cudaFuncAttributeMaxDynamicSharedMemorySize, SMEM128);
    cudaFuncSetAttribute(k_hgemm<128, 1>, cudaFuncAttributeMaxDynamicSharedMemorySize, SMEM128);
    cudaFuncSetAttribute(k_hgemm<64, 2>,  cudaFuncAttributeMaxDynamicSharedMemorySize, SMEM64);

    long long xq = (long long)N * CNFEAT / 4;
    long long nwcell = (long long)N * 32;
    int gy = cdiv(N, 128);

    // ---- fork: prep branch on s1 runs concurrently with cast/wt0/GEMM1 ----
    cudaEventRecord(evFork, 0);
    cudaStreamWaitEvent(s1, evFork, 0);

    // stream 0: GEMM1 dependency chain
    k_cast16<<<cdiv(xq, TB), TB>>>(x, p_x, xq);
    k_wt<<<cdiv(256 * 512, TB), TB>>>(W0, w0t, 512, 256);
    k_hgemm<128, 0><<<dim3(2, gy), 256, SMEM128>>>(p_x, w0t,
                                                   nullptr, nullptr, p_t,
                                                   N, 256, 512);

    // stream s1: everything independent of GEMM1
    k_wt<<<cdiv(256 * 256, TB), TB, 0, s1>>>(W1, w1t, 256, 256);
    k_wt<<<cdiv(256 * 256, TB), TB, 0, s1>>>(W2, w2t, 256, 256);
    k_wt<<<cdiv(512 * 256, TB), TB, 0, s1>>>(Wm0, wm0t, 256, 512);
    k_wt<<<cdiv(64 * 512, TB), TB, 0, s1>>>(Wm1, wm1t, 512, 64);
    k_lab_init<<<cdiv(N, TB), TB, 0, s1>>>(N);
    k_lab_set<<<cdiv(L, TB), TB, 0, s1>>>(idxl, y, L);
    k_zero_cnt<<<cdiv(N, TB), TB, 0, s1>>>(N);
    k_count<<<cdiv(E, TB), TB, 0, s1>>>(adj, E);
    k_scan<<<1, 1024, 0, s1>>>(N, E);
    k_dinv<<<cdiv(N, TB), TB, 0, s1>>>(N);
    k_fill<<<cdiv(E, TB), TB, 0, s1>>>(adj, E);

    // ---- join ----
    cudaEventRecord(evJoin, s1);
    cudaStreamWaitEvent(0, evJoin, 0);

    // layer 1 finish
    k_lab_add<<<cdiv(nwcell, TB), TB>>>(W0, p_t, N);
    k_agg_csr<<<cdiv(nwcell, TB), TB>>>(p_t, p_h, b0, N);

    // GCN layer 2
    k_hgemm<128, 0><<<dim3(2, gy), 256, SMEM128>>>(p_h, w1t,
                                                   nullptr, nullptr, p_t,
                                                   N, 256, 256);
    k_agg_csr<<<cdiv(nwcell, TB), TB>>>(p_t, p_h, b1, N);

    // GCN layer 3
    k_hgemm<128, 0><<<dim3(2, gy), 256, SMEM128>>>(p_h, w2t,
                                                   nullptr, nullptr, p_t,
                                                   N, 256, 256);
    k_agg_csr<<<cdiv(nwcell, TB), TB>>>(p_t, p_h, b2, N);

    // MLP head
    k_hgemm<128, 1><<<dim3(4, gy), 256, SMEM128>>>(p_h, wm0t,
                                                   nullptr, bm0, p_m,
                                                   N, 512, 256);
    k_hgemm<64, 2><<<dim3(1, gy), 256, SMEM64>>>(p_m, wm1t,
                                                 out, bm1, nullptr,
                                                 N, 64, 512);

    // log_softmax
    k_logsoftmax64<<<cdiv(nwcell, TB), TB>>>(out, N);
}

// round 17
// speedup vs baseline: 1.6926x; 1.0002x over previous
#include <cuda_runtime.h>
#include <cuda_fp16.h>
#include <cstdint>
#include <math.h>

// Problem constants (fixed shapes)
#define CN      100000
#define CE      1600000
#define CNFEAT  512
#define CNLABEL 64
#define CNHID   256
#define CHID2   512

// ---------------- scratch (device globals) ----------------------------------
__device__ __half g_t16 [(size_t)CN * CNHID];
__device__ __half g_h16 [(size_t)CN * CNHID];
__device__ __half g_m16 [(size_t)CN * CHID2];
__device__ __half g_x16 [(size_t)CN * CNFEAT];
__device__ __half g_w0t[256 * 512];
__device__ __half g_w1t[256 * 256];
__device__ __half g_w2t[256 * 256];
__device__ __half g_wm0t[512 * 256];
__device__ __half g_wm1t[64 * 512];
__device__ float  g_dinv[CN];
__device__ int    g_cnt[CN];
__device__ int    g_rowptr[CN + 1];
__device__ int    g_cursor[CN];
__device__ int    g_src[CE];
__device__ float  g_w[CE];
__device__ int    g_lab[CN];

// ---------------- CSR build --------------------------------------------------
__global__ void k_zero_cnt(int n) {
    int i = blockIdx.x * blockDim.x + threadIdx.x;
    if (i < n) g_cnt[i] = 0;
}
__global__ void k_count(const int* __restrict__ adj, int E) {
    int e = blockIdx.x * blockDim.x + threadIdx.x;
    if (e >= E) return;
    atomicAdd(&g_cnt[adj[E + e]], 1);
}
__global__ void k_scan(int n, int E) {
    __shared__ int bs[1024];
    int tid = threadIdx.x;
    int chunk = (n + 1023) / 1024;
    int lo = tid * chunk;
    int hi = lo + chunk; if (hi > n) hi = n; if (lo > n) lo = n;
    int s = 0;
    for (int i = lo; i < hi; i++) s += g_cnt[i];
    int mysum = s;
    bs[tid] = s;
    __syncthreads();
    for (int d = 1; d < 1024; d <<= 1) {
        int v = (tid >= d) ? bs[tid - d] : 0;
        __syncthreads();
        bs[tid] += v;
        __syncthreads();
    }
    int off = bs[tid] - mysum;
    for (int i = lo; i < hi; i++) {
        g_rowptr[i] = off;
        g_cursor[i] = off;
        off += g_cnt[i];
    }
    if (tid == 1023) g_rowptr[n] = E;
}
__global__ void k_dinv(int n) {
    int i = blockIdx.x * blockDim.x + threadIdx.x;
    if (i < n) g_dinv[i] = rsqrtf((float)g_cnt[i] + 2.0f);
}
__global__ void k_fill(const int* __restrict__ adj, int E) {
    int e = blockIdx.x * blockDim.x + threadIdx.x;
    if (e >= E) return;
    int src = adj[e];
    int dst = adj[E + e];
    int pos = atomicAdd(&g_cursor[dst], 1);
    g_src[pos] = src;
    g_w[pos] = g_dinv[src] * g_dinv[dst];
}

// ---------------- labels ------------------------------------------------------
__global__ void k_lab_init(int n) {
    int i = blockIdx.x * blockDim.x + threadIdx.x;
    if (i < n) g_lab[i] = -1;
}
__global__ void k_lab_set(const int* __restrict__ idxl, const int* __restrict__ y, int L) {
    int t = blockIdx.x * blockDim.x + threadIdx.x;
    if (t >= L) return;
    int node = idxl[t];
    g_lab[node] = y[node];
}
__global__ void k_lab_add(const float* __restrict__ W0, __half* __restrict__ t, int n) {
    int gt = blockIdx.x * blockDim.x + threadIdx.x;
    int warp = gt >> 5, lane = gt & 31;
    if (warp >= n) return;
    int lab = g_lab[warp];
    if (lab < 0) return;
    const float* wrow = W0 + (size_t)(CNFEAT + lab) * CNHID;
    __half* trow = t + (size_t)warp * CNHID;
#pragma unroll
    for (int k = 0; k < CNHID / 32; k++) {
        int i = k * 32 + lane;
        trow[i] = __float2half_rn(__half2float(trow[i]) + wrow[i]);
    }
}

// ---------------- cast / transpose helpers -------------------------------------
__global__ void k_cast16(const float* __restrict__ X, __half* __restrict__ H, long long nq) {
    long long i = (long long)blockIdx.x * blockDim.x + threadIdx.x;
    if (i >= nq) return;
    float4 v = ((const float4*)X)[i];
    ((__half2*)H)[2 * i]     = __floats2half2_rn(v.x, v.y);
    ((__half2*)H)[2 * i + 1] = __floats2half2_rn(v.z, v.w);
}

__global__ void k_wt(const float* __restrict__ W, __half* __restrict__ TH, int K, int N) {
    int idx = blockIdx.x * blockDim.x + threadIdx.x;
    if (idx >= N * K) return;
    int n = idx / K, k = idx % K;
    TH[idx] = __float2half_rn(W[(size_t)k * N + n]);
}

// ---------------- fused CSR aggregation (fp16 gathers, 4-edge unroll) ----------
__device__ __forceinline__ void h8acc(uint4 v, float w, float* a) {
    const __half2* h = (const __half2*)&v;
    float2 f0 = __half22float2(h[0]);
    float2 f1 = __half22float2(h[1]);
    float2 f2 = __half22float2(h[2]);
    float2 f3 = __half22float2(h[3]);
    a[0] = fmaf(w, f0.x, a[0]); a[1] = fmaf(w, f0.y, a[1]);
    a[2] = fmaf(w, f1.x, a[2]); a[3] = fmaf(w, f1.y, a[3]);
    a[4] = fmaf(w, f2.x, a[4]); a[5] = fmaf(w, f2.y, a[5]);
    a[6] = fmaf(w, f3.x, a[6]); a[7] = fmaf(w, f3.y, a[7]);
}

__global__ void __launch_bounds__(256)
k_agg_csr(const __half* __restrict__ t, __half* __restrict__ Oh,
          const float* __restrict__ bias, int n) {
    int warp = (blockIdx.x * blockDim.x + threadIdx.x) >> 5;
    int lane = threadIdx.x & 31;
    if (warp >= n) return;
    int beg = g_rowptr[warp];
    int end = g_rowptr[warp + 1];

    float acc[8];
    {
        float4 b0 = ((const float4*)bias)[2 * lane];
        float4 b1 = ((const float4*)bias)[2 * lane + 1];
        acc[0] = b0.x; acc[1] = b0.y; acc[2] = b0.z; acc[3] = b0.w;
        acc[4] = b1.x; acc[5] = b1.y; acc[6] = b1.z; acc[7] = b1.w;
    }
    {
        float d = g_dinv[warp];
        float sw = 2.0f * d * d;
        uint4 sv = ((const uint4*)(t + (size_t)warp * CNHID))[lane];
        h8acc(sv, sw, acc);
    }

    int e = beg;
    for (; e + 3 < end; e += 4) {
        int   si[4];
        float wi[4];
#pragma unroll
        for (int j = 0; j < 4; j++) { si[j] = g_src[e + j]; wi[j] = g_w[e + j]; }
        uint4 v[4];
#pragma unroll
        for (int j = 0; j < 4; j++)
            v[j] = ((const uint4*)(t + (size_t)si[j] * CNHID))[lane];
#pragma unroll
        for (int j = 0; j < 4; j++)
            h8acc(v[j], wi[j], acc);
    }
    for (; e < end; e++) {
        int sA = g_src[e];
        float wA = g_w[e];
        uint4 vA = ((const uint4*)(t + (size_t)sA * CNHID))[lane];
        h8acc(vA, wA, acc);
    }

    uint4 ov;
    __half2* oh = (__half2*)&ov;
    oh[0] = __floats2half2_rn(fmaxf(acc[0], 0.f), fmaxf(acc[1], 0.f));
    oh[1] = __floats2half2_rn(fmaxf(acc[2], 0.f), fmaxf(acc[3], 0.f));
    oh[2] = __floats2half2_rn(fmaxf(acc[4], 0.f), fmaxf(acc[5], 0.f));
    oh[3] = __floats2half2_rn(fmaxf(acc[6], 0.f), fmaxf(acc[7], 0.f));
    ((uint4*)(Oh + (size_t)warp * CNHID))[lane] = ov;
}

// ---------------- 1-term FP16 tensor-core GEMM ---------------------------------
__device__ __forceinline__ void mma_f16(float* c, const uint32_t* a, const uint32_t* b) {
    asm volatile(
        "mma.sync.aligned.m16n8k16.row.col.f32.f16.f16.f32 "
        "{%0,%1,%2,%3}, {%4,%5,%6,%7}, {%8,%9}, {%0,%1,%2,%3};\n"
        : "+f"(c[0]), "+f"(c[1]), "+f"(c[2]), "+f"(c[3])
        : "r"(a[0]), "r"(a[1]), "r"(a[2]), "r"(a[3]), "r"(b[0]), "r"(b[1]));
}
__device__ __forceinline__ void ldsm4(uint32_t& r0, uint32_t& r1, uint32_t& r2,
                                      uint32_t& r3, uint32_t addr) {
    asm volatile("ldmatrix.sync.aligned.m8n8.x4.shared.b16 {%0,%1,%2,%3}, [%4];"
                 : "=r"(r0), "=r"(r1), "=r"(r2), "=r"(r3) : "r"(addr));
}
__device__ __forceinline__ uint32_t s2u(const void* p) {
    uint32_t a;
    asm("{ .reg .u64 t; cvta.to.shared.u64 t, %1; cvt.u32.u64 %0, t; }" : "=r"(a) : "l"(p));
    return a;
}
__device__ __forceinline__ void cpa16(uint32_t dst, const void* src, bool pred) {
    asm volatile("cp.async.cg.shared.global [%0], [%1], 16, %2;"
                 :: "r"(dst), "l"(src), "r"(pred ? 16 : 0) : "memory");
}
__device__ __forceinline__ void cpa_commit() {
    asm volatile("cp.async.commit_group;" ::: "memory");
}
__device__ __forceinline__ void cpa_wait0() {
    asm volatile("cp.async.wait_group 0;" ::: "memory");
}

// C[M,N] = A @ B; A f16 [M][K]; B transposed f16 [N][K]. BM=128, BK=32.
// EPI: 0 plain -> fp16 Oh | 1 bias+ELU -> fp16 Oh | 3 bias + log_softmax(64) -> fp32 C
template <int BN, int EPI>
__global__ void __launch_bounds__(256)
k_hgemm(const __half* __restrict__ Ah,
        const __half* __restrict__ Bh,
        float* __restrict__ C, const float* __restrict__ bias,
        __half* __restrict__ Oh,
        int M, int N, int K) {
    constexpr int RSTR  = 80;                 // 64B data + 16B pad
    constexpr int ATILE = 128 * RSTR;
    constexpr int BTILE = BN * RSTR;
    constexpr int OFFB  = 2 * ATILE;
    constexpr int STAGE = OFFB + 2 * BTILE;   // fp32 staging for EPI3
    constexpr int NWN   = BN / 32;
    constexpr int MT    = (128 / (8 / NWN)) / 16;

    extern __shared__ char smem[];
    const uint32_t sb = s2u(smem);
    const int tid = threadIdx.x;
    const int wid = tid >> 5, lane = tid & 31;
    const int grp = lane >> 2, qid = lane & 3;
    const int warp_m = wid / NWN, warp_n = wid % NWN;
    const int row0 = blockIdx.y * 128;
    const int col0 = blockIdx.x * BN;

    const int lrow = lane & 15;
    const int lcol = (lane >> 4) * 16;

    float acc[MT][4][4];
#pragma unroll
    for (int i = 0; i < MT; i++)
#pragma unroll
        for (int j = 0; j < 4; j++)
#pragma unroll
            for (int c = 0; c < 4; c++) acc[i][j][c] = 0.0f;

    auto loadSlab = [&](int s, int b) {
        int k0 = s * 32;
#pragma unroll
        for (int i = 0; i < 2; i++) {
            int c = tid + i * 256;
            int r = c >> 2, p = c & 3;
            bool ok = (row0 + r) < M;
            int rr = ok ? (row0 + r) : (M - 1);
            size_t g = (size_t)rr * K + k0 + p * 8;
            cpa16(sb + b * ATILE + r * RSTR + p * 16, Ah + g, ok);
        }
#pragma unroll
        for (int i = 0; i < BN / 64; i++) {
            int c = tid + i * 256;
            int r = c >> 2, p = c & 3;
            size_t g = (size_t)(col0 + r) * K + k0 + p * 8;
            cpa16(sb + OFFB + b * BTILE + r * RSTR + p * 16, Bh + g, true);
        }
        cpa_commit();
    };

    auto computeSlab = [&](int b) {
        const uint32_t aB = sb + b * ATILE;
        const uint32_t bB = sb + OFFB + b * BTILE;
#pragma unroll
        for (int ks = 0; ks < 2; ks++) {
            const int kb = ks * 32 + lcol;
            uint32_t bh[4][2];
#pragma unroll
            for (int p = 0; p < 2; p++) {
                uint32_t addr = bB + (warp_n * 32 + p * 16 + lrow) * RSTR + kb;
                ldsm4(bh[2 * p][0], bh[2 * p + 1][0], bh[2 * p][1], bh[2 * p + 1][1], addr);
            }
#pragma unroll
            for (int mt = 0; mt < MT; mt++) {
                uint32_t addr = aB + (warp_m * (MT * 16) + mt * 16 + lrow) * RSTR + kb;
                uint32_t ah[4];
                ldsm4(ah[0], ah[1], ah[2], ah[3], addr);
#pragma unroll
                for (int nt = 0; nt < 4; nt++)
                    mma_f16(acc[mt][nt], ah, bh[nt]);
            }
        }
    };

    const int ns = K / 32;
    loadSlab(0, 0);
    cpa_wait0();
    __syncthreads();
    for (int s = 0; s < ns; s++) {
        int b = s & 1;
        if (s + 1 < ns) loadSlab(s + 1, b ^ 1);
        computeSlab(b);
        if (s + 1 < ns) {
            cpa_wait0();
            __syncthreads();
        }
    }

    // ---- epilogue ----
    float* stage = (float*)(smem + STAGE);    // [128][64] for EPI3
#pragma unroll
    for (int mt = 0; mt < MT; mt++) {
        int rbase = row0 + warp_m * (MT * 16) + mt * 16 + grp;
#pragma unroll
        for (int nt = 0; nt < 4; nt++) {
            int cb = col0 + warp_n * 32 + nt * 8 + 2 * qid;
#pragma unroll
            for (int half = 0; half < 2; half++) {
                int r = rbase + half * 8;
                if (EPI != 3 && r >= M) continue;
                float v0 = acc[mt][nt][half * 2 + 0];
                float v1 = acc[mt][nt][half * 2 + 1];
                if (EPI >= 1) { v0 += bias[cb]; v1 += bias[cb + 1]; }
                if (EPI == 1) {
                    v0 = v0 > 0.0f ? v0 : expm1f(v0);
                    v1 = v1 > 0.0f ? v1 : expm1f(v1);
                }
                if (EPI == 3) {
                    int rl = r - row0;
                    stage[rl * 64 + (cb - col0)] = v0;
                    stage[rl * 64 + (cb - col0) + 1] = v1;
                } else if (EPI == 0 || EPI == 1) {
                    *(__half2*)&Oh[(size_t)r * N + cb] = __floats2half2_rn(v0, v1);
                }
            }
        }
    }

    if (EPI == 3) {
        __syncthreads();
        // 8 warps x 16 rows: per-row log_softmax over 64 classes
#pragma unroll
        for (int i = 0; i < 16; i++) {
            int rl = wid * 16 + i;
            int r = row0 + rl;
            if (r >= M) continue;
            float v0 = stage[rl * 64 + lane];
            float v1 = stage[rl * 64 + lane + 32];
            float m = fmaxf(v0, v1);
#pragma unroll
            for (int o = 16; o; o >>= 1) m = fmaxf(m, __shfl_xor_sync(0xffffffffu, m, o));
            float sum = expf(v0 - m) + expf(v1 - m);
#pragma unroll
            for (int o = 16; o; o >>= 1) sum += __shfl_xor_sync(0xffffffffu, sum, o);
            float l = m + logf(sum);
            C[(size_t)r * 64 + lane] = v0 - l;
            C[(size_t)r * 64 + lane + 32] = v1 - l;
        }
    }
}

// ---------------- host orchestration ---------------------------------------
static inline int cdiv(long long a, long long b) { return (int)((a + b - 1) / b); }

extern "C" void kernel_launch(void* const* d_in, const int* in_sizes, int n_in,
                              void* d_out, int out_size) {
    const float* x    = (const float*)d_in[0];
    const int*   y    = (const int*)  d_in[1];
    const int*   adj  = (const int*)  d_in[3];
    const int*   idxl = (const int*)  d_in[4];
    const float* W0  = (const float*)d_in[6];
    const float* b0  = (const float*)d_in[7];
    const float* W1  = (const float*)d_in[8];
    const float* b1  = (const float*)d_in[9];
    const float* W2  = (const float*)d_in[10];
    const float* b2  = (const float*)d_in[11];
    const float* Wm0 = (const float*)d_in[12];
    const float* bm0 = (const float*)d_in[13];
    const float* Wm1 = (const float*)d_in[14];
    const float* bm1 = (const float*)d_in[15];

    int N = in_sizes[1];
    int E = in_sizes[3] / 2;
    int L = in_sizes[4];
    float* out = (float*)d_out;

    __half *p_t, *p_h, *p_m, *p_x;
    __half *w0t, *w1t, *w2t, *wm0t, *wm1t;
    cudaGetSymbolAddress((void**)&p_t, g_t16);
    cudaGetSymbolAddress((void**)&p_h, g_h16);
    cudaGetSymbolAddress((void**)&p_m, g_m16);
    cudaGetSymbolAddress((void**)&p_x, g_x16);
    cudaGetSymbolAddress((void**)&w0t,  g_w0t);
    cudaGetSymbolAddress((void**)&w1t,  g_w1t);
    cudaGetSymbolAddress((void**)&w2t,  g_w2t);
    cudaGetSymbolAddress((void**)&wm0t, g_wm0t);
    cudaGetSymbolAddress((void**)&wm1t, g_wm1t);

    // lazy one-time stream/event creation (outside capture on the correctness call)
    static cudaStream_t s1 = nullptr;
    static cudaEvent_t evFork = nullptr, evJoin = nullptr, evWt0 = nullptr;
    if (s1 == nullptr) {
        cudaStreamCreateWithFlags(&s1, cudaStreamNonBlocking);
        cudaEventCreateWithFlags(&evFork, cudaEventDisableTiming);
        cudaEventCreateWithFlags(&evJoin, cudaEventDisableTiming);
        cudaEventCreateWithFlags(&evWt0,  cudaEventDisableTiming);
    }

    const int TB = 256;
    const int SMEM128 = 2 * 128 * 80 + 2 * 128 * 80;                // 40960
    const int SMEM64F = 2 * 128 * 80 + 2 * 64 * 80 + 128 * 64 * 4;  // 63488
    cudaFuncSetAttribute(k_hgemm<128, 0>, cudaFuncAttributeMaxDynamicSharedMemorySize, SMEM128);
    cudaFuncSetAttribute(k_hgemm<128, 1>, cudaFuncAttributeMaxDynamicSharedMemorySize, SMEM128);
    cudaFuncSetAttribute(k_hgemm<64, 3>,  cudaFuncAttributeMaxDynamicSharedMemorySize, SMEM64F);

    long long xq = (long long)N * CNFEAT / 4;
    long long nwcell = (long long)N * 32;
    int gy = cdiv(N, 128);

    // ---- fork: prep branch on s1 (wt0 first, has its own early join) ----
    cudaEventRecord(evFork, 0);
    cudaStreamWaitEvent(s1, evFork, 0);

    // stream s1: wt0 first (GEMM1 needs it), then the rest of the prep
    k_wt<<<cdiv(256 * 512, TB), TB, 0, s1>>>(W0, w0t, 512, 256);
    cudaEventRecord(evWt0, s1);
    k_wt<<<cdiv(256 * 256, TB), TB, 0, s1>>>(W1, w1t, 256, 256);
    k_wt<<<cdiv(256 * 256, TB), TB, 0, s1>>>(W2, w2t, 256, 256);
    k_wt<<<cdiv(512 * 256, TB), TB, 0, s1>>>(Wm0, wm0t, 256, 512);
    k_wt<<<cdiv(64 * 512, TB), TB, 0, s1>>>(Wm1, wm1t, 512, 64);
    k_lab_init<<<cdiv(N, TB), TB, 0, s1>>>(N);
    k_lab_set<<<cdiv(L, TB), TB, 0, s1>>>(idxl, y, L);
    k_zero_cnt<<<cdiv(N, TB), TB, 0, s1>>>(N);
    k_count<<<cdiv(E, TB), TB, 0, s1>>>(adj, E);
    k_scan<<<1, 1024, 0, s1>>>(N, E);
    k_dinv<<<cdiv(N, TB), TB, 0, s1>>>(N);
    k_fill<<<cdiv(E, TB), TB, 0, s1>>>(adj, E);

    // stream 0: cast x (overlaps wt0), then GEMM1 after wt0 ready
    k_cast16<<<cdiv(xq, TB), TB>>>(x, p_x, xq);
    cudaStreamWaitEvent(0, evWt0, 0);
    k_hgemm<128, 0><<<dim3(2, gy), 256, SMEM128>>>(p_x, w0t,
                                                   nullptr, nullptr, p_t,
                                                   N, 256, 512);

    // ---- join ----
    cudaEventRecord(evJoin, s1);
    cudaStreamWaitEvent(0, evJoin, 0);

    // layer 1 finish
    k_lab_add<<<cdiv(nwcell, TB), TB>>>(W0, p_t, N);
    k_agg_csr<<<cdiv(nwcell, TB), TB>>>(p_t, p_h, b0, N);

    // GCN layer 2
    k_hgemm<128, 0><<<dim3(2, gy), 256, SMEM128>>>(p_h, w1t,
                                                   nullptr, nullptr, p_t,
                                                   N, 256, 256);
    k_agg_csr<<<cdiv(nwcell, TB), TB>>>(p_t, p_h, b1, N);

    // GCN layer 3
    k_hgemm<128, 0><<<dim3(2, gy), 256, SMEM128>>>(p_h, w2t,
                                                   nullptr, nullptr, p_t,
                                                   N, 256, 256);
    k_agg_csr<<<cdiv(nwcell, TB), TB>>>(p_t, p_h, b2, N);

    // MLP head: MLP1, then MLP2 fused with log_softmax
    k_hgemm<128, 1><<<dim3(4, gy), 256, SMEM128>>>(p_h, wm0t,
                                                   nullptr, bm0, p_m,
                                                   N, 512, 256);
    k_hgemm<64, 3><<<dim3(1, gy), 256, SMEM64F>>>(p_m, wm1t,
                                                  out, bm1, nullptr,
                                                  N, 64, 512);
}